// round 3
// baseline (speedup 1.0000x reference)
#include <cuda_runtime.h>
#include <math.h>

#define BATCH 16
#define NCLS  20
#define NGT   64
#define N3    16384
#define N4    4096
#define N5    1024
#define NTOT  (N3 + N4 + N5)     // 21504
#define TOPK  1000
#define MAXDET 100
#define SCORE_THR 0.3f
#define IOU_THR   0.5f
#define NBIN  4096
#define TB0   0x3E99999Au        // float bits of 0.3f

// ---------------- scratch (device globals; zero-initialized at load) --------
__device__ float        g_scores[BATCH * NTOT];
__device__ float4       g_boxes [BATCH * NTOT];
__device__ int          g_cls   [BATCH * NTOT];
__device__ unsigned int g_hist  [BATCH * NBIN];     // zeroed by k_select after use
__device__ float4       g_sbox  [BATCH * 1024];     // sorted original boxes
__device__ float        g_sscore[BATCH * 1024];     // sorted scores
__device__ float4       g_nbox  [BATCH * 1024];     // class-offset boxes
__device__ float        g_narea [BATCH * 1024];     // areas of offset boxes
__device__ int          g_nvalid[BATCH];
__device__ unsigned int g_sup   [BATCH * TOPK * 32]; // suppression bitmask rows

__device__ __forceinline__ float sigmoidf_(float x) {
    if (x >= 0.f) return 1.f / (1.f + expf(-x));
    float e = expf(x);
    return e / (1.f + e);
}
__device__ __forceinline__ unsigned int fenc(float f) {
    unsigned int u = __float_as_uint(f);
    return (u & 0x80000000u) ? ~u : (u | 0x80000000u);
}
__device__ __forceinline__ float fdec(unsigned int e) {
    return (e & 0x80000000u) ? __uint_as_float(e & 0x7FFFFFFFu) : __uint_as_float(~e);
}

// =========== kernel 1: targets + score/decode + score histogram =============
__global__ __launch_bounds__(256) void k_fused(
    const float* __restrict__ l3, const float* __restrict__ l4, const float* __restrict__ l5,
    const float* __restrict__ gt,
    const float* __restrict__ c3, const float* __restrict__ c4, const float* __restrict__ c5,
    const float* __restrict__ r3, const float* __restrict__ r4, const float* __restrict__ r5,
    const float* __restrict__ t3, const float* __restrict__ t4, const float* __restrict__ t5,
    float* __restrict__ od, float* __restrict__ oc)
{
    const int b   = blockIdx.y;
    const int tid = threadIdx.x;
    const int i   = blockIdx.x * 256 + tid;          // 84*256 == NTOT exactly

    __shared__ float4 sbox[NGT];
    __shared__ float  sarea[NGT];
    __shared__ int    swcnt[2];
    __shared__ int    scnt;

    // ---- load + order-preserving compaction of valid GT boxes ----
    float x0 = 0.f, y0 = 0.f, x1 = 0.f, y1 = 0.f;
    bool  val = false;
    int   pref = 0;
    if (tid < 64) {
        const float* g = gt + (size_t)b * NGT * 5 + tid * 5;
        x0 = g[0]; y0 = g[1]; x1 = g[2]; y1 = g[3];
        val = (x0 >= 0.f);
        int lane = tid & 31, w = tid >> 5;
        unsigned m = __ballot_sync(0xFFFFFFFFu, val);
        pref = __popc(m & ((1u << lane) - 1));
        if (lane == 0) swcnt[w] = __popc(m);
    }
    __syncthreads();
    if (tid < 64 && val) {
        int base = (tid >= 32) ? swcnt[0] : 0;
        int pos  = base + pref;
        sbox[pos]  = make_float4(x0, y0, x1, y1);
        sarea[pos] = (x1 - x0) * (y1 - y0);
    }
    if (tid == 0) scnt = swcnt[0] + swcnt[1];
    __syncthreads();

    float xc, yc, lower, upper, stride;
    int j, n;
    const float *cls, *reg, *ctr;
    if (i < N3)           { j = i;            n = N3; xc = l3[2*j]; yc = l3[2*j+1]; lower = 0.f;   upper = 64.f;     stride = 8.f;  cls = c3; reg = r3; ctr = t3; }
    else if (i < N3 + N4) { j = i - N3;       n = N4; xc = l4[2*j]; yc = l4[2*j+1]; lower = 64.f;  upper = 128.f;    stride = 16.f; cls = c4; reg = r4; ctr = t4; }
    else                  { j = i - N3 - N4;  n = N5; xc = l5[2*j]; yc = l5[2*j+1]; lower = 128.f; upper = INFINITY; stride = 32.f; cls = c5; reg = r5; ctr = t5; }

    // ---- GT matching: min-area among eligible, first-wins on ties ----
    float bestA = INFINITY;
    int   besti = -1;
    const int nv = scnt;
    for (int m = 0; m < nv; m++) {
        float4 bb = sbox[m];
        float l = xc - bb.x, t = yc - bb.y, r = bb.z - xc, bo = bb.w - yc;
        float mn = fminf(fminf(l, t), fminf(r, bo));
        float mx = fmaxf(fmaxf(l, t), fmaxf(r, bo));
        float a  = sarea[m];
        if (mn > 0.f && mx > lower && mx < upper && a < bestA) { bestA = a; besti = m; }
    }

    float d0, d1, d2, d3, ctrt;
    if (besti < 0) {
        d0 = d1 = d2 = d3 = -1.f; ctrt = -1.f;
    } else {
        float4 bb = sbox[besti];
        d0 = (xc - bb.x) / stride;
        d1 = (yc - bb.y) / stride;
        d2 = (bb.z - xc) / stride;
        d3 = (bb.w - yc) / stride;
        float num = fminf(d0, d2) * fminf(d1, d3);
        float den = fmaxf(d0, d2) * fmaxf(d1, d3);
        ctrt = sqrtf(num / den);
    }
    size_t base = (size_t)(b * NTOT + i);
    od[base*4+0] = d0; od[base*4+1] = d1; od[base*4+2] = d2; od[base*4+3] = d3;
    oc[base] = ctrt;

    // ---- class-max score + decode ----
    const float4* cp4 = reinterpret_cast<const float4*>(cls + ((size_t)b * n + j) * NCLS);
    float best = -INFINITY; int bc = 0;
    #pragma unroll
    for (int c4i = 0; c4i < 5; c4i++) {
        float4 v = cp4[c4i];
        if (v.x > best) { best = v.x; bc = c4i*4+0; }
        if (v.y > best) { best = v.y; bc = c4i*4+1; }
        if (v.z > best) { best = v.z; bc = c4i*4+2; }
        if (v.w > best) { best = v.w; bc = c4i*4+3; }
    }
    float sc = sqrtf(sigmoidf_(best) * sigmoidf_(ctr[(size_t)b * n + j]));

    float4 rp = reinterpret_cast<const float4*>(reg)[(size_t)b * n + j];
    float e0 = fmaxf(rp.x, 0.f) * stride;
    float e1 = fmaxf(rp.y, 0.f) * stride;
    float e2 = fmaxf(rp.z, 0.f) * stride;
    float e3 = fmaxf(rp.w, 0.f) * stride;

    int o = b * NTOT + i;
    g_scores[o] = sc;
    g_boxes[o]  = make_float4(xc - e0, yc - e1, xc + e2, yc + e3);
    g_cls[o]    = bc;

    unsigned int sb = __float_as_uint(sc);
    if (sb > TB0) atomicAdd(&g_hist[b * NBIN + ((sb >> 13) & (NBIN-1))], 1u);
}

// =========== kernel 2: per-batch exact top-1000 sort ========================
__global__ __launch_bounds__(1024) void k_select(void)
{
    __shared__ unsigned long long keys[2048];
    __shared__ __align__(16) unsigned int shist[NBIN];
    __shared__ unsigned int wsum[32], wAbove[32];
    __shared__ unsigned int sCnt, sMaxU, sNv;
    __shared__ int sB, sB2, sTotal, sCand, sAbove;

    const int b    = blockIdx.x;
    const int tid  = threadIdx.x;
    const int lane = tid & 31, wid = tid >> 5;
    const float* sc = g_scores + b * NTOT;

    // ---- phase 1: pull histogram, zero global copy for next replay ----
    for (int k = tid; k < NBIN; k += 1024) {
        unsigned v = g_hist[b * NBIN + k];
        shist[k] = v;
        g_hist[b * NBIN + k] = 0;
    }
    if (tid == 0) { sB = 0; sB2 = 0; sCand = 0; sAbove = 0; sCnt = 0; sNv = 0; sMaxU = fenc(0.0f); }
    __syncthreads();

    // ---- phase 2: parallel suffix scan -> threshold bin ----
    unsigned s0 = shist[4*tid], s1 = shist[4*tid+1], s2 = shist[4*tid+2], s3 = shist[4*tid+3];
    unsigned st = s0 + s1 + s2 + s3;
    unsigned inc = st;
    #pragma unroll
    for (int off = 1; off < 32; off <<= 1) {
        unsigned v = __shfl_down_sync(0xFFFFFFFFu, inc, off);
        if (lane + off < 32) inc += v;
    }
    if (lane == 0) wsum[wid] = inc;
    __syncthreads();
    if (tid < 32) {
        unsigned v = wsum[tid], winc = v;
        #pragma unroll
        for (int off = 1; off < 32; off <<= 1) {
            unsigned u = __shfl_down_sync(0xFFFFFFFFu, winc, off);
            if (tid + off < 32) winc += u;
        }
        wAbove[tid] = winc - v;
        if (tid == 0) sTotal = (int)winc;
    }
    __syncthreads();
    {
        unsigned cum = wAbove[wid] + (inc - st);
        unsigned hh[4] = { s3, s2, s1, s0 };
        #pragma unroll
        for (int q = 0; q < 4; q++) {
            if (cum < TOPK && cum + hh[q] >= TOPK) {
                sB = 4*tid + 3 - q; sCand = (int)(cum + hh[q]); sAbove = (int)cum;
            }
            cum += hh[q];
        }
    }
    __syncthreads();
    if (sTotal < TOPK) {
        if (tid == 0) sCand = sTotal;
        __syncthreads();
    }
    const int B = sB;
    int B2 = 0;

    // ---- rare refinement: boundary bin too fat for the 2048-key buffer ----
    if (sCand > 2040) {
        for (int k = tid; k < 2048; k += 1024) ((unsigned*)keys)[k] = 0;
        __syncthreads();
        unsigned* h2 = (unsigned*)keys;
        for (int k = tid; k < NTOT; k += 1024) {
            unsigned bits = __float_as_uint(sc[k]);
            if (bits > TB0 && (int)((bits >> 13) & (NBIN-1)) == B)
                atomicAdd(&h2[(bits >> 2) & 2047u], 1u);
        }
        __syncthreads();
        if (tid == 0) {
            unsigned cum2 = (unsigned)sAbove; int bb = 0;
            for (int k = 2047; k >= 0; k--) {
                if (cum2 + h2[k] >= TOPK) { bb = k; break; }
                cum2 += h2[k];
            }
            sB2 = bb;
        }
        __syncthreads();
        B2 = sB2;
        __syncthreads();
    }

    // ---- phase 3: compaction (warp-aggregated) ----
    for (int k = tid; k < NTOT; k += 1024) {
        unsigned bits = __float_as_uint(sc[k]);
        int bin = (int)((bits >> 13) & (NBIN-1));
        bool cand = (bits > TB0) && (bin > B || (bin == B && (int)((bits >> 2) & 2047u) >= B2));
        unsigned m = __ballot_sync(0xFFFFFFFFu, cand);
        int leader = __ffs(m) - 1;
        unsigned base = 0;
        if (cand && lane == leader) base = atomicAdd(&sCnt, (unsigned)__popc(m));
        base = __shfl_sync(0xFFFFFFFFu, base, leader < 0 ? 0 : leader);
        if (cand) {
            unsigned pos = base + __popc(m & ((1u << lane) - 1));
            if (pos < 2048)
                keys[pos] = ((unsigned long long)bits << 32)
                          | (unsigned long long)(0xFFFFFFFFu - (unsigned)k);
        }
    }
    __syncthreads();
    const unsigned S = min(sCnt, 2048u);
    const unsigned NSORT = (S <= 1024u) ? 1024u : 2048u;
    for (unsigned k = tid; k < NSORT; k += 1024)
        if (k >= S) keys[k] = 0ull;
    __syncthreads();

    // ---- phase 4: bitonic sort ascending (rank r at keys[NSORT-1-r]) ----
    // j<=8 steps are intra-warp (owner = idx&~j; cross-warp only when 2j>=32)
    for (unsigned ksz = 2; ksz <= NSORT; ksz <<= 1) {
        for (unsigned jj = ksz >> 1; jj > 0; jj >>= 1) {
            for (unsigned idx = tid; idx < NSORT; idx += 1024) {
                unsigned ixj = idx ^ jj;
                if (ixj > idx) {
                    unsigned long long a = keys[idx], c = keys[ixj];
                    bool up = ((idx & ksz) == 0);
                    if (up ? (a > c) : (a < c)) { keys[idx] = c; keys[ixj] = a; }
                }
            }
            if (jj > 16) __syncthreads();
            else if (jj == 16) __syncthreads();   // next step reads j=16-written data? keep safe
            else __syncwarp();
        }
        __syncthreads();                          // between ksz phases (cross-warp reads at new large j)
    }

    // ---- phase 5: gather top-1000, max_coord, write sorted arrays ----
    unsigned long long key = (tid < TOPK) ? keys[NSORT - 1 - tid] : 0ull;
    float s = __uint_as_float((unsigned)(key >> 32));
    unsigned gidx = 0xFFFFFFFFu - (unsigned)key;
    bool valid = (tid < TOPK) && (key != 0ull);
    float4 bx = make_float4(0.f, 0.f, 0.f, 0.f);
    int cid = 0;
    if (valid) { bx = g_boxes[b * NTOT + gidx]; cid = g_cls[b * NTOT + gidx]; }
    float mrow = valid ? fmaxf(fmaxf(bx.x, bx.y), fmaxf(bx.z, bx.w)) : 0.f;
    {   // warp-reduce max then one atomic per warp
        unsigned e = fenc(mrow);
        #pragma unroll
        for (int off = 16; off > 0; off >>= 1)
            e = max(e, __shfl_down_sync(0xFFFFFFFFu, e, off));
        if (lane == 0) atomicMax(&sMaxU, e);
        unsigned vm = __ballot_sync(0xFFFFFFFFu, valid);
        if (lane == 0) atomicAdd(&sNv, (unsigned)__popc(vm));
    }
    __syncthreads();
    const float offmul = fdec(sMaxU) + 1.0f;
    if (tid < TOPK) {
        float o = (float)cid * offmul;
        float4 nb = make_float4(bx.x + o, bx.y + o, bx.z + o, bx.w + o);
        g_sbox  [b * 1024 + tid] = bx;
        g_sscore[b * 1024 + tid] = s;
        g_nbox  [b * 1024 + tid] = nb;
        g_narea [b * 1024 + tid] = (nb.z - nb.x) * (nb.w - nb.y);
    }
    if (tid == 0) g_nvalid[b] = (int)min(sNv, (unsigned)TOPK);
}

// =========== kernel 3: suppression matrix (chip-wide) =======================
__global__ __launch_bounds__(512) void k_iou(void)
{
    __shared__ float4 nb[TOPK];
    __shared__ float  ar[TOPK];
    const int b   = blockIdx.y;
    const int tid = threadIdx.x;
    for (int k = tid; k < TOPK; k += 512) {
        nb[k] = g_nbox [b * 1024 + k];
        ar[k] = g_narea[b * 1024 + k];
    }
    __syncthreads();
    for (int t = tid; t < 4096; t += 512) {
        int w  = t >> 7;                       // word 0..31
        int il = t & 127;
        int i  = blockIdx.x * 128 + il;        // row
        if (i >= TOPK) continue;
        float4 pb = nb[i];
        float  pa = ar[i];
        unsigned bits = 0;
        int jb = w << 5;
        #pragma unroll
        for (int jj = 0; jj < 32; jj++) {
            float4 qb = nb[jb + jj];           // broadcast across lanes
            float xx1 = fmaxf(pb.x, qb.x);
            float yy1 = fmaxf(pb.y, qb.y);
            float xx2 = fminf(pb.z, qb.z);
            float yy2 = fminf(pb.w, qb.w);
            float inter = fmaxf(xx2 - xx1, 0.f) * fmaxf(yy2 - yy1, 0.f);
            float iou = inter / (pa + ar[jb + jj] - inter);
            if (!(iou <= IOU_THR)) bits |= (1u << jj);   // NaN-safe
        }
        g_sup[(b * TOPK + i) * 32 + w] = bits;
    }
}

// =========== kernel 4: serial greedy walk (1 warp) + det write ==============
__global__ __launch_bounds__(1024) void k_walk(float* __restrict__ dets)
{
    extern __shared__ unsigned int sup_s[];     // TOPK*32 words = 125 KB
    __shared__ unsigned int skeep[32];
    const int b   = blockIdx.x;
    const int tid = threadIdx.x;

    for (int k = tid; k < TOPK * 32; k += 1024)
        sup_s[k] = g_sup[b * TOPK * 32 + k];
    __syncthreads();

    if (tid < 32) {
        const int lane = tid;
        const int nv = g_nvalid[b];
        unsigned removed = 0, keepm = 0;
        int kept = 0;
        for (int w = 0; w < 32 && kept < MAXDET; w++) {
            int base = w << 5;
            if (base >= nv) break;
            unsigned cur = __shfl_sync(0xFFFFFFFFu, removed, w);
            int lim = min(32, nv - base);
            for (int bit = 0; bit < lim; bit++) {
                if (!((cur >> bit) & 1u)) {
                    if (lane == w) keepm |= (1u << bit);
                    kept++;
                    if (kept >= MAXDET) break;
                    removed |= sup_s[(base + bit) * 32 + lane];
                    cur = __shfl_sync(0xFFFFFFFFu, removed, w);
                }
            }
        }
        skeep[lane] = keepm;
    }
    __syncthreads();

    if (tid < TOPK) {
        float* det = dets + (size_t)b * TOPK * 5 + (size_t)tid * 5;
        if ((skeep[tid >> 5] >> (tid & 31)) & 1u) {
            float4 bx = g_sbox[b * 1024 + tid];
            det[0] = bx.x; det[1] = bx.y; det[2] = bx.z; det[3] = bx.w;
            det[4] = g_sscore[b * 1024 + tid];
        } else {
            det[0] = 0.f; det[1] = 0.f; det[2] = 0.f; det[3] = 0.f; det[4] = 0.f;
        }
    }
}

// ---------------- launch ----------------------------------------------------
extern "C" void kernel_launch(void* const* d_in, const int* in_sizes, int n_in,
                              void* d_out, int out_size)
{
    const float* l3 = (const float*)d_in[0];
    const float* l4 = (const float*)d_in[1];
    const float* l5 = (const float*)d_in[2];
    const float* gt = (const float*)d_in[3];

    const float *c3, *c4, *c5, *r3, *r4, *r5, *t3, *t4, *t5;
    if (in_sizes[5] == BATCH * N3 * 4) {
        c3 = (const float*)d_in[4];  r3 = (const float*)d_in[5];  t3 = (const float*)d_in[6];
        c4 = (const float*)d_in[7];  r4 = (const float*)d_in[8];  t4 = (const float*)d_in[9];
        c5 = (const float*)d_in[10]; r5 = (const float*)d_in[11]; t5 = (const float*)d_in[12];
    } else {
        c3 = (const float*)d_in[4];  c4 = (const float*)d_in[5];  c5 = (const float*)d_in[6];
        r3 = (const float*)d_in[7];  r4 = (const float*)d_in[8];  r5 = (const float*)d_in[9];
        t3 = (const float*)d_in[10]; t4 = (const float*)d_in[11]; t5 = (const float*)d_in[12];
    }

    float* out       = (float*)d_out;
    float* out_dets  = out;                                   // [16,1000,5]
    float* out_delta = out + (size_t)BATCH * TOPK * 5;        // [16,21504,4]
    float* out_ctr   = out_delta + (size_t)BATCH * NTOT * 4;  // [16,21504]

    static int smem_set = 0;
    (void)smem_set;
    const int walk_smem = TOPK * 32 * sizeof(unsigned int);   // 128000 B
    cudaFuncSetAttribute(k_walk, cudaFuncAttributeMaxDynamicSharedMemorySize, walk_smem);

    dim3 grd(NTOT / 256, BATCH);
    k_fused <<<grd, 256>>>(l3, l4, l5, gt, c3, c4, c5, r3, r4, r5, t3, t4, t5,
                           out_delta, out_ctr);
    k_select<<<BATCH, 1024>>>();
    k_iou   <<<dim3(8, BATCH), 512>>>();
    k_walk  <<<BATCH, 1024, walk_smem>>>(out_dets);
}

// round 4
// speedup vs baseline: 1.5168x; 1.5168x over previous
#include <cuda_runtime.h>
#include <math.h>

#define BATCH 16
#define NCLS  20
#define NGT   64
#define N3    16384
#define N4    4096
#define N5    1024
#define NTOT  (N3 + N4 + N5)     // 21504
#define TOPK  1000
#define MAXDET 100
#define SCORE_THR 0.3f
#define IOU_THR   0.5f
#define NBIN  4096
#define TB0   0x3E99999Au        // float bits of 0.3f
#define SUPSTRIDE 1033           // bank-conflict-free transposed stride

// ---------------- scratch (device globals; zero-initialized at load) --------
__device__ float        g_scores[BATCH * NTOT];
__device__ float4       g_boxes [BATCH * NTOT];
__device__ int          g_cls   [BATCH * NTOT];
__device__ unsigned int g_hist  [BATCH * NBIN];   // zeroed by k_post after use

__device__ __forceinline__ float sigmoidf_(float x) {
    if (x >= 0.f) return 1.f / (1.f + expf(-x));
    float e = expf(x);
    return e / (1.f + e);
}
__device__ __forceinline__ unsigned int fenc(float f) {
    unsigned int u = __float_as_uint(f);
    return (u & 0x80000000u) ? ~u : (u | 0x80000000u);
}
__device__ __forceinline__ float fdec(unsigned int e) {
    return (e & 0x80000000u) ? __uint_as_float(e & 0x7FFFFFFFu) : __uint_as_float(~e);
}

// =========== kernel 1: targets + score/decode + score histogram =============
__global__ __launch_bounds__(256) void k_fused(
    const float* __restrict__ l3, const float* __restrict__ l4, const float* __restrict__ l5,
    const float* __restrict__ gt,
    const float* __restrict__ c3, const float* __restrict__ c4, const float* __restrict__ c5,
    const float* __restrict__ r3, const float* __restrict__ r4, const float* __restrict__ r5,
    const float* __restrict__ t3, const float* __restrict__ t4, const float* __restrict__ t5,
    float* __restrict__ od, float* __restrict__ oc)
{
    const int b   = blockIdx.y;
    const int tid = threadIdx.x;
    const int i   = blockIdx.x * 256 + tid;          // 84*256 == NTOT exactly

    __shared__ float4 sbox[NGT];
    __shared__ float  sarea[NGT];
    __shared__ int    swcnt[2];
    __shared__ int    scnt;

    // ---- load + order-preserving compaction of valid GT boxes ----
    float x0 = 0.f, y0 = 0.f, x1 = 0.f, y1 = 0.f;
    bool  val = false;
    int   pref = 0;
    if (tid < 64) {
        const float* g = gt + (size_t)b * NGT * 5 + tid * 5;
        x0 = g[0]; y0 = g[1]; x1 = g[2]; y1 = g[3];
        val = (x0 >= 0.f);
        int lane = tid & 31, w = tid >> 5;
        unsigned m = __ballot_sync(0xFFFFFFFFu, val);
        pref = __popc(m & ((1u << lane) - 1));
        if (lane == 0) swcnt[w] = __popc(m);
    }
    __syncthreads();
    if (tid < 64 && val) {
        int base = (tid >= 32) ? swcnt[0] : 0;
        int pos  = base + pref;
        sbox[pos]  = make_float4(x0, y0, x1, y1);
        sarea[pos] = (x1 - x0) * (y1 - y0);
    }
    if (tid == 0) scnt = swcnt[0] + swcnt[1];
    __syncthreads();

    float xc, yc, lower, upper, stride;
    int j, n;
    const float *cls, *reg, *ctr;
    if (i < N3)           { j = i;            n = N3; xc = l3[2*j]; yc = l3[2*j+1]; lower = 0.f;   upper = 64.f;     stride = 8.f;  cls = c3; reg = r3; ctr = t3; }
    else if (i < N3 + N4) { j = i - N3;       n = N4; xc = l4[2*j]; yc = l4[2*j+1]; lower = 64.f;  upper = 128.f;    stride = 16.f; cls = c4; reg = r4; ctr = t4; }
    else                  { j = i - N3 - N4;  n = N5; xc = l5[2*j]; yc = l5[2*j+1]; lower = 128.f; upper = INFINITY; stride = 32.f; cls = c5; reg = r5; ctr = t5; }

    // ---- GT matching: min-area among eligible, first-wins on ties ----
    float bestA = INFINITY;
    int   besti = -1;
    const int nv = scnt;
    for (int m = 0; m < nv; m++) {
        float4 bb = sbox[m];
        float l = xc - bb.x, t = yc - bb.y, r = bb.z - xc, bo = bb.w - yc;
        float mn = fminf(fminf(l, t), fminf(r, bo));
        float mx = fmaxf(fmaxf(l, t), fmaxf(r, bo));
        float a  = sarea[m];
        if (mn > 0.f && mx > lower && mx < upper && a < bestA) { bestA = a; besti = m; }
    }

    float d0, d1, d2, d3, ctrt;
    if (besti < 0) {
        d0 = d1 = d2 = d3 = -1.f; ctrt = -1.f;
    } else {
        float4 bb = sbox[besti];
        d0 = (xc - bb.x) / stride;
        d1 = (yc - bb.y) / stride;
        d2 = (bb.z - xc) / stride;
        d3 = (bb.w - yc) / stride;
        float num = fminf(d0, d2) * fminf(d1, d3);
        float den = fmaxf(d0, d2) * fmaxf(d1, d3);
        ctrt = sqrtf(num / den);
    }
    size_t base = (size_t)(b * NTOT + i);
    od[base*4+0] = d0; od[base*4+1] = d1; od[base*4+2] = d2; od[base*4+3] = d3;
    oc[base] = ctrt;

    // ---- class-max score + decode ----
    const float4* cp4 = reinterpret_cast<const float4*>(cls + ((size_t)b * n + j) * NCLS);
    float best = -INFINITY; int bc = 0;
    #pragma unroll
    for (int c4i = 0; c4i < 5; c4i++) {
        float4 v = cp4[c4i];
        if (v.x > best) { best = v.x; bc = c4i*4+0; }
        if (v.y > best) { best = v.y; bc = c4i*4+1; }
        if (v.z > best) { best = v.z; bc = c4i*4+2; }
        if (v.w > best) { best = v.w; bc = c4i*4+3; }
    }
    float sc = sqrtf(sigmoidf_(best) * sigmoidf_(ctr[(size_t)b * n + j]));

    float4 rp = reinterpret_cast<const float4*>(reg)[(size_t)b * n + j];
    float e0 = fmaxf(rp.x, 0.f) * stride;
    float e1 = fmaxf(rp.y, 0.f) * stride;
    float e2 = fmaxf(rp.z, 0.f) * stride;
    float e3 = fmaxf(rp.w, 0.f) * stride;

    int o = b * NTOT + i;
    g_scores[o] = sc;
    g_boxes[o]  = make_float4(xc - e0, yc - e1, xc + e2, yc + e3);
    g_cls[o]    = bc;

    unsigned int sb = __float_as_uint(sc);
    if (sb > TB0) atomicAdd(&g_hist[b * NBIN + ((sb >> 13) & (NBIN-1))], 1u);
}

// ---- suppression sub-matrix: rows/cols [0,L), transposed sup[w*1033+p] ----
__device__ __forceinline__ void compute_sup(
    unsigned int* __restrict__ sup, const float4* __restrict__ nbox,
    const float* __restrict__ areas, int L, int lshift, int tid)
{
    const int total = (L >> 5) * L;
    for (int u = tid; u < total; u += 1024) {
        int p = u & (L - 1);
        int w = u >> lshift;
        float4 pb = nbox[p];
        float  pa = areas[p];
        unsigned bits = 0;
        int jb = w << 5;
        #pragma unroll 8
        for (int jj = 0; jj < 32; ++jj) {
            float4 qb = nbox[jb + jj];          // uniform j across warp -> broadcast
            float ar  = areas[jb + jj];
            float xx1 = fmaxf(pb.x, qb.x);
            float yy1 = fmaxf(pb.y, qb.y);
            float xx2 = fminf(pb.z, qb.z);
            float yy2 = fminf(pb.w, qb.w);
            float inter = fmaxf(xx2 - xx1, 0.f) * fmaxf(yy2 - yy1, 0.f);
            float iou = inter / (pa + ar - inter);
            if (!(iou <= IOU_THR)) bits |= (1u << jj);    // NaN-safe
        }
        sup[w * SUPSTRIDE + p] = bits;
    }
}

// ---- warp-serial greedy walk over sorted order (ffs jumping) ----
__device__ __forceinline__ void walk(
    const unsigned int* __restrict__ sup, int nv, int L,
    unsigned int* __restrict__ skeep, int* __restrict__ esc, int lane)
{
    unsigned removed = 0, keepm = 0;
    int kept = 0; bool bad = false;
    for (int w = 0; w < 32 && kept < MAXDET; ++w) {
        int base = w << 5;
        if (base >= nv) break;
        if (base >= L) { bad = true; break; }
        int lim = min(32, nv - base);
        unsigned vmask = (lim == 32) ? 0xFFFFFFFFu : ((1u << lim) - 1u);
        unsigned cur  = __shfl_sync(0xFFFFFFFFu, removed, w);
        unsigned cand = ~cur & vmask;
        while (cand && kept < MAXDET) {
            int bit = __ffs(cand) - 1;
            int p = base + bit;
            if (lane == w) keepm |= (1u << bit);
            ++kept;
            removed |= sup[lane * SUPSTRIDE + p];
            cur  = __shfl_sync(0xFFFFFFFFu, removed, w);
            cand = ~cur & vmask & (0xFFFFFFFEu << bit);
        }
    }
    skeep[lane] = keepm;
    if (lane == 0 && bad) *esc = 1;
}

// =========== kernel 2: top-1000 sort + in-smem NMS + det write ==============
// dynamic smem layout (total 169088 B):
//   [0,132224)        sup (32 x 1033 words)  — aliases shist[4096] (early phases)
//   [132224,148608)   keys[2048] u64
//   [148608,164992)   nbox[1024] float4
//   [164992,169088)   areas[1024] float
__global__ __launch_bounds__(1024) void k_post(float* __restrict__ dets)
{
    extern __shared__ unsigned char dyn[];
    unsigned int*       shist = (unsigned int*)dyn;
    unsigned int*       sup   = (unsigned int*)dyn;
    unsigned long long* keys  = (unsigned long long*)(dyn + 132224);
    float4*             nbox  = (float4*)(dyn + 148608);
    float*              areas = (float*)(dyn + 164992);

    __shared__ unsigned int wsum[32], wAbove[32], skeep[32];
    __shared__ unsigned int sCnt, sMaxU, sNv;
    __shared__ int sB, sB2, sTotal, sCand, sAbove, sEsc;

    const int b    = blockIdx.x;
    const int tid  = threadIdx.x;
    const int lane = tid & 31, wid = tid >> 5;
    const float* sc = g_scores + b * NTOT;

    // ---- phase 1: pull histogram, zero global copy for next replay ----
    for (int k = tid; k < NBIN; k += 1024) {
        unsigned v = g_hist[b * NBIN + k];
        shist[k] = v;
        g_hist[b * NBIN + k] = 0;
    }
    if (tid == 0) { sB = 0; sB2 = 0; sCand = 0; sAbove = 0; sCnt = 0; sNv = 0; sEsc = 0; sMaxU = fenc(0.0f); }
    __syncthreads();

    // ---- phase 2: parallel suffix scan -> threshold bin ----
    unsigned s0 = shist[4*tid], s1 = shist[4*tid+1], s2 = shist[4*tid+2], s3 = shist[4*tid+3];
    unsigned st = s0 + s1 + s2 + s3;
    unsigned inc = st;
    #pragma unroll
    for (int off = 1; off < 32; off <<= 1) {
        unsigned v = __shfl_down_sync(0xFFFFFFFFu, inc, off);
        if (lane + off < 32) inc += v;
    }
    if (lane == 0) wsum[wid] = inc;
    __syncthreads();
    if (tid < 32) {
        unsigned v = wsum[tid], winc = v;
        #pragma unroll
        for (int off = 1; off < 32; off <<= 1) {
            unsigned u = __shfl_down_sync(0xFFFFFFFFu, winc, off);
            if (tid + off < 32) winc += u;
        }
        wAbove[tid] = winc - v;
        if (tid == 0) sTotal = (int)winc;
    }
    __syncthreads();
    {
        unsigned cum = wAbove[wid] + (inc - st);
        unsigned hh[4] = { s3, s2, s1, s0 };
        #pragma unroll
        for (int q = 0; q < 4; q++) {
            if (cum < TOPK && cum + hh[q] >= TOPK) {
                sB = 4*tid + 3 - q; sCand = (int)(cum + hh[q]); sAbove = (int)cum;
            }
            cum += hh[q];
        }
    }
    __syncthreads();
    if (sTotal < TOPK) {
        if (tid == 0) sCand = sTotal;
        __syncthreads();
    }
    const int B = sB;
    int B2 = 0;

    // ---- rare refinement: boundary bin too fat for the 2048-key buffer ----
    if (sCand > 2040) {
        unsigned* h2 = (unsigned*)keys;
        for (int k = tid; k < 2048; k += 1024) h2[k] = 0;
        __syncthreads();
        for (int k = tid; k < NTOT; k += 1024) {
            unsigned bits = __float_as_uint(sc[k]);
            if (bits > TB0 && (int)((bits >> 13) & (NBIN-1)) == B)
                atomicAdd(&h2[(bits >> 2) & 2047u], 1u);
        }
        __syncthreads();
        if (tid == 0) {
            unsigned cum2 = (unsigned)sAbove; int bb = 0;
            for (int k = 2047; k >= 0; k--) {
                if (cum2 + h2[k] >= TOPK) { bb = k; break; }
                cum2 += h2[k];
            }
            sB2 = bb;
        }
        __syncthreads();
        B2 = sB2;
        __syncthreads();
    }

    // ---- phase 3: compaction (warp-aggregated) ----
    for (int k = tid; k < NTOT; k += 1024) {
        unsigned bits = __float_as_uint(sc[k]);
        int bin = (int)((bits >> 13) & (NBIN-1));
        bool cand = (bits > TB0) && (bin > B || (bin == B && (int)((bits >> 2) & 2047u) >= B2));
        unsigned m = __ballot_sync(0xFFFFFFFFu, cand);
        int leader = __ffs(m) - 1;
        unsigned base = 0;
        if (cand && lane == leader) base = atomicAdd(&sCnt, (unsigned)__popc(m));
        base = __shfl_sync(0xFFFFFFFFu, base, leader < 0 ? 0 : leader);
        if (cand) {
            unsigned pos = base + __popc(m & ((1u << lane) - 1));
            if (pos < 2048)
                keys[pos] = ((unsigned long long)bits << 32)
                          | (unsigned long long)(0xFFFFFFFFu - (unsigned)k);
        }
    }
    __syncthreads();
    const unsigned S = min(sCnt, 2048u);
    const unsigned NSORT = (S <= 1024u) ? 1024u : 2048u;
    for (unsigned k = tid; k < NSORT; k += 1024)
        if (k >= S) keys[k] = 0ull;
    __syncthreads();

    // ---- phase 4: bitonic sort ascending (rank r at keys[NSORT-1-r]) ----
    for (unsigned ksz = 2; ksz <= NSORT; ksz <<= 1) {
        for (unsigned jj = ksz >> 1; jj > 0; jj >>= 1) {
            for (unsigned idx = tid; idx < NSORT; idx += 1024) {
                unsigned ixj = idx ^ jj;
                if (ixj > idx) {
                    unsigned long long a = keys[idx], c = keys[ixj];
                    bool up = ((idx & ksz) == 0);
                    if (up ? (a > c) : (a < c)) { keys[idx] = c; keys[ixj] = a; }
                }
            }
            if (jj >= 16) __syncthreads();
            else __syncwarp();
        }
        __syncthreads();
    }

    // ---- phase 5: gather top-1000, max_coord, offset boxes into smem ----
    unsigned long long key = (tid < TOPK) ? keys[NSORT - 1 - tid] : 0ull;
    float s = __uint_as_float((unsigned)(key >> 32));
    unsigned gidx = 0xFFFFFFFFu - (unsigned)key;
    bool valid = (tid < TOPK) && (key != 0ull);
    float4 bx = make_float4(0.f, 0.f, 0.f, 0.f);
    int cid = 0;
    if (valid) { bx = g_boxes[b * NTOT + gidx]; cid = g_cls[b * NTOT + gidx]; }
    float mrow = valid ? fmaxf(fmaxf(bx.x, bx.y), fmaxf(bx.z, bx.w)) : 0.f;
    {
        unsigned e = fenc(mrow);
        #pragma unroll
        for (int off = 16; off > 0; off >>= 1)
            e = max(e, __shfl_down_sync(0xFFFFFFFFu, e, off));
        if (lane == 0) atomicMax(&sMaxU, e);
        unsigned vm = __ballot_sync(0xFFFFFFFFu, valid);
        if (lane == 0) atomicAdd(&sNv, (unsigned)__popc(vm));
    }
    __syncthreads();
    const float offmul = fdec(sMaxU) + 1.0f;
    if (tid < TOPK) {
        float o = (float)cid * offmul;
        float4 nb = make_float4(bx.x + o, bx.y + o, bx.z + o, bx.w + o);
        nbox[tid]  = nb;
        areas[tid] = (nb.z - nb.x) * (nb.w - nb.y);
    }
    const int nv = 0;  (void)nv;
    __syncthreads();
    const int NV = (int)min(sNv, (unsigned)TOPK);

    // ---- phase 6: adaptive sup matrix + warp walk ----
    compute_sup(sup, nbox, areas, 256, 8, tid);        // 64K IOUs, ~0.7us
    __syncthreads();
    if (tid < 32) walk(sup, NV, 256, skeep, &sEsc, lane);
    __syncthreads();
    if (sEsc) {                                        // rare: cursor crossed 256
        compute_sup(sup, nbox, areas, 1024, 10, tid);  // full matrix
        __syncthreads();
        if (tid < 32) walk(sup, NV, 1024, skeep, &sEsc, lane);
        __syncthreads();
    }

    // ---- phase 7: write detections ----
    if (tid < TOPK) {
        float* det = dets + (size_t)b * TOPK * 5 + (size_t)tid * 5;
        if ((skeep[tid >> 5] >> (tid & 31)) & 1u) {
            det[0] = bx.x; det[1] = bx.y; det[2] = bx.z; det[3] = bx.w; det[4] = s;
        } else {
            det[0] = 0.f; det[1] = 0.f; det[2] = 0.f; det[3] = 0.f; det[4] = 0.f;
        }
    }
}

// ---------------- launch ----------------------------------------------------
extern "C" void kernel_launch(void* const* d_in, const int* in_sizes, int n_in,
                              void* d_out, int out_size)
{
    const float* l3 = (const float*)d_in[0];
    const float* l4 = (const float*)d_in[1];
    const float* l5 = (const float*)d_in[2];
    const float* gt = (const float*)d_in[3];

    const float *c3, *c4, *c5, *r3, *r4, *r5, *t3, *t4, *t5;
    if (in_sizes[5] == BATCH * N3 * 4) {
        c3 = (const float*)d_in[4];  r3 = (const float*)d_in[5];  t3 = (const float*)d_in[6];
        c4 = (const float*)d_in[7];  r4 = (const float*)d_in[8];  t4 = (const float*)d_in[9];
        c5 = (const float*)d_in[10]; r5 = (const float*)d_in[11]; t5 = (const float*)d_in[12];
    } else {
        c3 = (const float*)d_in[4];  c4 = (const float*)d_in[5];  c5 = (const float*)d_in[6];
        r3 = (const float*)d_in[7];  r4 = (const float*)d_in[8];  r5 = (const float*)d_in[9];
        t3 = (const float*)d_in[10]; t4 = (const float*)d_in[11]; t5 = (const float*)d_in[12];
    }

    float* out       = (float*)d_out;
    float* out_dets  = out;                                   // [16,1000,5]
    float* out_delta = out + (size_t)BATCH * TOPK * 5;        // [16,21504,4]
    float* out_ctr   = out_delta + (size_t)BATCH * NTOT * 4;  // [16,21504]

    const int post_smem = 169088;
    cudaFuncSetAttribute(k_post, cudaFuncAttributeMaxDynamicSharedMemorySize, post_smem);

    dim3 grd(NTOT / 256, BATCH);
    k_fused<<<grd, 256>>>(l3, l4, l5, gt, c3, c4, c5, r3, r4, r5, t3, t4, t5,
                          out_delta, out_ctr);
    k_post <<<BATCH, 1024, post_smem>>>(out_dets);
}

// round 5
// speedup vs baseline: 1.5659x; 1.0324x over previous
#include <cuda_runtime.h>
#include <math.h>

#define BATCH 16
#define NCLS  20
#define NGT   64
#define N3    16384
#define N4    4096
#define N5    1024
#define NTOT  (N3 + N4 + N5)     // 21504
#define SEG   (NTOT / 32)        // 672 elements per warp segment
#define TOPK  1000
#define MAXDET 100
#define SCORE_THR 0.3f
#define IOU_THR   0.5f
#define NBIN  4096
#define TB0   0x3E99999Au        // float bits of 0.3f
#define SUPSTRIDE 1033           // bank-conflict-free transposed stride

// ---------------- scratch (device globals; zero-initialized at load) --------
__device__ float        g_scores[BATCH * NTOT];
__device__ float4       g_boxes [BATCH * NTOT];
__device__ int          g_cls   [BATCH * NTOT];
__device__ unsigned int g_hist  [BATCH * NBIN];   // zeroed by k_sel after use
__device__ float4       g_sbox  [BATCH * 1024];   // sorted original boxes
__device__ float        g_sscore[BATCH * 1024];   // sorted scores
__device__ float4       g_nbox  [BATCH * 1024];   // class-offset boxes
__device__ float        g_narea [BATCH * 1024];   // areas of offset boxes
__device__ int          g_nvalid[BATCH];

__device__ __forceinline__ float sigmoidf_(float x) {
    if (x >= 0.f) return 1.f / (1.f + expf(-x));
    float e = expf(x);
    return e / (1.f + e);
}
__device__ __forceinline__ unsigned int fenc(float f) {
    unsigned int u = __float_as_uint(f);
    return (u & 0x80000000u) ? ~u : (u | 0x80000000u);
}
__device__ __forceinline__ float fdec(unsigned int e) {
    return (e & 0x80000000u) ? __uint_as_float(e & 0x7FFFFFFFu) : __uint_as_float(~e);
}

// =========== kernel 1: targets + score/decode + score histogram =============
__global__ __launch_bounds__(256) void k_fused(
    const float* __restrict__ l3, const float* __restrict__ l4, const float* __restrict__ l5,
    const float* __restrict__ gt,
    const float* __restrict__ c3, const float* __restrict__ c4, const float* __restrict__ c5,
    const float* __restrict__ r3, const float* __restrict__ r4, const float* __restrict__ r5,
    const float* __restrict__ t3, const float* __restrict__ t4, const float* __restrict__ t5,
    float* __restrict__ od, float* __restrict__ oc)
{
    const int b   = blockIdx.y;
    const int tid = threadIdx.x;
    const int i   = blockIdx.x * 256 + tid;          // 84*256 == NTOT exactly

    __shared__ float4 sbox[NGT];
    __shared__ float  sarea[NGT];
    __shared__ int    swcnt[2];
    __shared__ int    scnt;

    float x0 = 0.f, y0 = 0.f, x1 = 0.f, y1 = 0.f;
    bool  val = false;
    int   pref = 0;
    if (tid < 64) {
        const float* g = gt + (size_t)b * NGT * 5 + tid * 5;
        x0 = g[0]; y0 = g[1]; x1 = g[2]; y1 = g[3];
        val = (x0 >= 0.f);
        int lane = tid & 31, w = tid >> 5;
        unsigned m = __ballot_sync(0xFFFFFFFFu, val);
        pref = __popc(m & ((1u << lane) - 1));
        if (lane == 0) swcnt[w] = __popc(m);
    }
    __syncthreads();
    if (tid < 64 && val) {
        int base = (tid >= 32) ? swcnt[0] : 0;
        int pos  = base + pref;
        sbox[pos]  = make_float4(x0, y0, x1, y1);
        sarea[pos] = (x1 - x0) * (y1 - y0);
    }
    if (tid == 0) scnt = swcnt[0] + swcnt[1];
    __syncthreads();

    float xc, yc, lower, upper, stride;
    int j, n;
    const float *cls, *reg, *ctr;
    if (i < N3)           { j = i;            n = N3; xc = l3[2*j]; yc = l3[2*j+1]; lower = 0.f;   upper = 64.f;     stride = 8.f;  cls = c3; reg = r3; ctr = t3; }
    else if (i < N3 + N4) { j = i - N3;       n = N4; xc = l4[2*j]; yc = l4[2*j+1]; lower = 64.f;  upper = 128.f;    stride = 16.f; cls = c4; reg = r4; ctr = t4; }
    else                  { j = i - N3 - N4;  n = N5; xc = l5[2*j]; yc = l5[2*j+1]; lower = 128.f; upper = INFINITY; stride = 32.f; cls = c5; reg = r5; ctr = t5; }

    float bestA = INFINITY;
    int   besti = -1;
    const int nv = scnt;
    for (int m = 0; m < nv; m++) {
        float4 bb = sbox[m];
        float l = xc - bb.x, t = yc - bb.y, r = bb.z - xc, bo = bb.w - yc;
        float mn = fminf(fminf(l, t), fminf(r, bo));
        float mx = fmaxf(fmaxf(l, t), fmaxf(r, bo));
        float a  = sarea[m];
        if (mn > 0.f && mx > lower && mx < upper && a < bestA) { bestA = a; besti = m; }
    }

    float d0, d1, d2, d3, ctrt;
    if (besti < 0) {
        d0 = d1 = d2 = d3 = -1.f; ctrt = -1.f;
    } else {
        float4 bb = sbox[besti];
        d0 = (xc - bb.x) / stride;
        d1 = (yc - bb.y) / stride;
        d2 = (bb.z - xc) / stride;
        d3 = (bb.w - yc) / stride;
        float num = fminf(d0, d2) * fminf(d1, d3);
        float den = fmaxf(d0, d2) * fmaxf(d1, d3);
        ctrt = sqrtf(num / den);
    }
    size_t base = (size_t)(b * NTOT + i);
    od[base*4+0] = d0; od[base*4+1] = d1; od[base*4+2] = d2; od[base*4+3] = d3;
    oc[base] = ctrt;

    const float4* cp4 = reinterpret_cast<const float4*>(cls + ((size_t)b * n + j) * NCLS);
    float best = -INFINITY; int bc = 0;
    #pragma unroll
    for (int c4i = 0; c4i < 5; c4i++) {
        float4 v = cp4[c4i];
        if (v.x > best) { best = v.x; bc = c4i*4+0; }
        if (v.y > best) { best = v.y; bc = c4i*4+1; }
        if (v.z > best) { best = v.z; bc = c4i*4+2; }
        if (v.w > best) { best = v.w; bc = c4i*4+3; }
    }
    float sc = sqrtf(sigmoidf_(best) * sigmoidf_(ctr[(size_t)b * n + j]));

    float4 rp = reinterpret_cast<const float4*>(reg)[(size_t)b * n + j];
    float e0 = fmaxf(rp.x, 0.f) * stride;
    float e1 = fmaxf(rp.y, 0.f) * stride;
    float e2 = fmaxf(rp.z, 0.f) * stride;
    float e3 = fmaxf(rp.w, 0.f) * stride;

    int o = b * NTOT + i;
    g_scores[o] = sc;
    g_boxes[o]  = make_float4(xc - e0, yc - e1, xc + e2, yc + e3);
    g_cls[o]    = bc;

    unsigned int sb = __float_as_uint(sc);
    if (sb > TB0) atomicAdd(&g_hist[b * NBIN + ((sb >> 13) & (NBIN-1))], 1u);
}

// =========== kernel 2: threshold + compaction + sort + gather ===============
__global__ __launch_bounds__(1024) void k_sel(void)
{
    __shared__ __align__(16) unsigned int shist[NBIN];       // 16 KB
    __shared__ unsigned long long keys[2048];                 // 16 KB
    __shared__ unsigned int wsum[32], wAbove[32], wcnt[32], woff[32];
    __shared__ unsigned int sMaxU;
    __shared__ int sB, sB2, sTotal, sCand, sAbove, sS;

    const int b    = blockIdx.x;
    const int tid  = threadIdx.x;
    const int lane = tid & 31, wid = tid >> 5;
    const float* sc = g_scores + b * NTOT;

    // ---- phase 1: pull histogram, zero global copy for next replay ----
    for (int k = tid; k < NBIN; k += 1024) {
        unsigned v = g_hist[b * NBIN + k];
        shist[k] = v;
        g_hist[b * NBIN + k] = 0;
    }
    if (tid == 0) { sB = 0; sB2 = 0; sCand = 0; sAbove = 0; sMaxU = fenc(0.0f); }
    __syncthreads();

    // ---- phase 2: parallel suffix scan -> threshold bin ----
    unsigned s0 = shist[4*tid], s1 = shist[4*tid+1], s2 = shist[4*tid+2], s3 = shist[4*tid+3];
    unsigned st = s0 + s1 + s2 + s3;
    unsigned inc = st;
    #pragma unroll
    for (int off = 1; off < 32; off <<= 1) {
        unsigned v = __shfl_down_sync(0xFFFFFFFFu, inc, off);
        if (lane + off < 32) inc += v;
    }
    if (lane == 0) wsum[wid] = inc;
    __syncthreads();
    if (tid < 32) {
        unsigned v = wsum[tid], winc = v;
        #pragma unroll
        for (int off = 1; off < 32; off <<= 1) {
            unsigned u = __shfl_down_sync(0xFFFFFFFFu, winc, off);
            if (tid + off < 32) winc += u;
        }
        wAbove[tid] = winc - v;
        if (tid == 0) sTotal = (int)winc;
    }
    __syncthreads();
    {
        unsigned cum = wAbove[wid] + (inc - st);
        unsigned hh[4] = { s3, s2, s1, s0 };
        #pragma unroll
        for (int q = 0; q < 4; q++) {
            if (cum < TOPK && cum + hh[q] >= TOPK) {
                sB = 4*tid + 3 - q; sCand = (int)(cum + hh[q]); sAbove = (int)cum;
            }
            cum += hh[q];
        }
    }
    __syncthreads();
    if (sTotal < TOPK) {
        if (tid == 0) sCand = sTotal;
        __syncthreads();
    }
    const int B = sB;
    int B2 = 0;

    // ---- rare refinement: boundary bin too fat for the 2048-key buffer ----
    if (sCand > 2040) {
        unsigned* h2 = (unsigned*)keys;
        for (int k = tid; k < 2048; k += 1024) h2[k] = 0;
        __syncthreads();
        for (int k = tid; k < NTOT; k += 1024) {
            unsigned bits = __float_as_uint(sc[k]);
            if (bits > TB0 && (int)((bits >> 13) & (NBIN-1)) == B)
                atomicAdd(&h2[(bits >> 2) & 2047u], 1u);
        }
        __syncthreads();
        if (tid == 0) {
            unsigned cum2 = (unsigned)sAbove; int bb = 0;
            for (int k = 2047; k >= 0; k--) {
                if (cum2 + h2[k] >= TOPK) { bb = k; break; }
                cum2 += h2[k];
            }
            sB2 = bb;
        }
        __syncthreads();
        B2 = sB2;
        __syncthreads();
    }

    // ---- phase 3: segmented compaction, zero contended atomics ----
    // warp w owns contiguous segment [w*672, (w+1)*672): 21 coalesced iterations
    const float* seg = sc + wid * SEG;
    unsigned mycnt = 0;
    #pragma unroll
    for (int it = 0; it < SEG / 32; it++) {
        unsigned bits = __float_as_uint(seg[it * 32 + lane]);
        int bin = (int)((bits >> 13) & (NBIN-1));
        bool cand = (bits > TB0) && (bin > B || (bin == B && (int)((bits >> 2) & 2047u) >= B2));
        mycnt += __popc(__ballot_sync(0xFFFFFFFFu, cand));
    }
    if (lane == 0) wcnt[wid] = mycnt;
    __syncthreads();
    if (tid < 32) {                      // exclusive scan of 32 warp counts
        unsigned v = wcnt[tid], x = v;
        #pragma unroll
        for (int off = 1; off < 32; off <<= 1) {
            unsigned u = __shfl_up_sync(0xFFFFFFFFu, x, off);
            if (tid >= off) x += u;
        }
        woff[tid] = x - v;
        if (tid == 31) sS = (int)x;
    }
    __syncthreads();
    {
        unsigned wo = woff[wid];
        #pragma unroll
        for (int it = 0; it < SEG / 32; it++) {
            int k = wid * SEG + it * 32 + lane;
            unsigned bits = __float_as_uint(seg[it * 32 + lane]);   // L1 hit
            int bin = (int)((bits >> 13) & (NBIN-1));
            bool cand = (bits > TB0) && (bin > B || (bin == B && (int)((bits >> 2) & 2047u) >= B2));
            unsigned m = __ballot_sync(0xFFFFFFFFu, cand);
            if (cand) {
                unsigned pos = wo + __popc(m & ((1u << lane) - 1));
                if (pos < 2048)
                    keys[pos] = ((unsigned long long)bits << 32)
                              | (unsigned long long)(0xFFFFFFFFu - (unsigned)k);
            }
            wo += __popc(m);
        }
    }
    __syncthreads();
    const unsigned S = min((unsigned)sS, 2048u);
    const unsigned NSORT = (S <= 1024u) ? 1024u : 2048u;
    for (unsigned k = tid; k < NSORT; k += 1024)
        if (k >= S) keys[k] = 0ull;
    __syncthreads();

    // ---- phase 4: bitonic sort ascending (rank r at keys[NSORT-1-r]) ----
    for (unsigned ksz = 2; ksz <= NSORT; ksz <<= 1) {
        for (unsigned jj = ksz >> 1; jj > 0; jj >>= 1) {
            for (unsigned idx = tid; idx < NSORT; idx += 1024) {
                unsigned ixj = idx ^ jj;
                if (ixj > idx) {
                    unsigned long long a = keys[idx], c = keys[ixj];
                    bool up = ((idx & ksz) == 0);
                    if (up ? (a > c) : (a < c)) { keys[idx] = c; keys[ixj] = a; }
                }
            }
            if (jj >= 16) __syncthreads();
            else __syncwarp();
        }
        __syncthreads();
    }

    // ---- phase 5: gather top-1000, max_coord, write sorted arrays ----
    unsigned long long key = (tid < TOPK) ? keys[NSORT - 1 - tid] : 0ull;
    float s = __uint_as_float((unsigned)(key >> 32));
    unsigned gidx = 0xFFFFFFFFu - (unsigned)key;
    bool valid = (tid < TOPK) && (key != 0ull);
    float4 bx = make_float4(0.f, 0.f, 0.f, 0.f);
    int cid = 0;
    if (valid) { bx = g_boxes[b * NTOT + gidx]; cid = g_cls[b * NTOT + gidx]; }
    float mrow = valid ? fmaxf(fmaxf(bx.x, bx.y), fmaxf(bx.z, bx.w)) : 0.f;
    {
        unsigned e = fenc(mrow);
        #pragma unroll
        for (int off = 16; off > 0; off >>= 1)
            e = max(e, __shfl_down_sync(0xFFFFFFFFu, e, off));
        if (lane == 0) atomicMax(&sMaxU, e);
    }
    int NV = __syncthreads_count(valid);     // barrier + block-wide count
    const float offmul = fdec(sMaxU) + 1.0f;
    if (tid < TOPK) {
        float o = (float)cid * offmul;
        float4 nb = make_float4(bx.x + o, bx.y + o, bx.z + o, bx.w + o);
        g_sbox  [b * 1024 + tid] = bx;
        g_sscore[b * 1024 + tid] = s;
        g_nbox  [b * 1024 + tid] = nb;
        g_narea [b * 1024 + tid] = (nb.z - nb.x) * (nb.w - nb.y);
    }
    if (tid == 0) g_nvalid[b] = min(NV, TOPK);
}

// ---- suppression sub-matrix: rows/cols [0,L), transposed sup[w*1033+p] ----
__device__ __forceinline__ void compute_sup(
    unsigned int* __restrict__ sup, const float4* __restrict__ nbox,
    const float* __restrict__ areas, int L, int lshift, int tid)
{
    const int total = (L >> 5) * L;
    for (int u = tid; u < total; u += 1024) {
        int p = u & (L - 1);
        int w = u >> lshift;
        float4 pb = nbox[p];
        float  pa = areas[p];
        unsigned bits = 0;
        int jb = w << 5;
        #pragma unroll 8
        for (int jj = 0; jj < 32; ++jj) {
            float4 qb = nbox[jb + jj];
            float ar  = areas[jb + jj];
            float xx1 = fmaxf(pb.x, qb.x);
            float yy1 = fmaxf(pb.y, qb.y);
            float xx2 = fminf(pb.z, qb.z);
            float yy2 = fminf(pb.w, qb.w);
            float inter = fmaxf(xx2 - xx1, 0.f) * fmaxf(yy2 - yy1, 0.f);
            float iou = inter / (pa + ar - inter);
            if (!(iou <= IOU_THR)) bits |= (1u << jj);    // NaN-safe
        }
        sup[w * SUPSTRIDE + p] = bits;
    }
}

// ---- warp-serial greedy walk over sorted order (ffs jumping) ----
__device__ __forceinline__ void walk(
    const unsigned int* __restrict__ sup, int nv, int L,
    unsigned int* __restrict__ skeep, int* __restrict__ esc, int lane)
{
    unsigned removed = 0, keepm = 0;
    int kept = 0; bool bad = false;
    for (int w = 0; w < 32 && kept < MAXDET; ++w) {
        int base = w << 5;
        if (base >= nv) break;
        if (base >= L) { bad = true; break; }
        int lim = min(32, nv - base);
        unsigned vmask = (lim == 32) ? 0xFFFFFFFFu : ((1u << lim) - 1u);
        unsigned cur  = __shfl_sync(0xFFFFFFFFu, removed, w);
        unsigned cand = ~cur & vmask;
        while (cand && kept < MAXDET) {
            int bit = __ffs(cand) - 1;
            int p = base + bit;
            if (lane == w) keepm |= (1u << bit);
            ++kept;
            removed |= sup[lane * SUPSTRIDE + p];
            cur  = __shfl_sync(0xFFFFFFFFu, removed, w);
            cand = ~cur & vmask & (0xFFFFFFFEu << bit);
        }
    }
    skeep[lane] = keepm;
    if (lane == 0 && bad) *esc = 1;
}

// =========== kernel 3: sup matrix + walk + det write ========================
__global__ __launch_bounds__(1024) void k_nms(float* __restrict__ dets)
{
    extern __shared__ unsigned int sup[];                 // 32*1033 words
    __shared__ __align__(16) float4 nbox[1024];
    __shared__ float  areas[1024];
    __shared__ unsigned int skeep[32];
    __shared__ int sEsc;

    const int b   = blockIdx.x;
    const int tid = threadIdx.x;

    nbox[tid]  = g_nbox [b * 1024 + tid];
    areas[tid] = g_narea[b * 1024 + tid];
    if (tid == 0) sEsc = 0;
    __syncthreads();
    const int NV = g_nvalid[b];

    compute_sup(sup, nbox, areas, 256, 8, tid);
    __syncthreads();
    if (tid < 32) walk(sup, NV, 256, skeep, &sEsc, tid);
    __syncthreads();
    if (sEsc) {
        compute_sup(sup, nbox, areas, 1024, 10, tid);
        __syncthreads();
        if (tid < 32) walk(sup, NV, 1024, skeep, &sEsc, tid);
        __syncthreads();
    }

    if (tid < TOPK) {
        float* det = dets + (size_t)b * TOPK * 5 + (size_t)tid * 5;
        if ((skeep[tid >> 5] >> (tid & 31)) & 1u) {
            float4 bx = g_sbox[b * 1024 + tid];
            det[0] = bx.x; det[1] = bx.y; det[2] = bx.z; det[3] = bx.w;
            det[4] = g_sscore[b * 1024 + tid];
        } else {
            det[0] = 0.f; det[1] = 0.f; det[2] = 0.f; det[3] = 0.f; det[4] = 0.f;
        }
    }
}

// ---------------- launch ----------------------------------------------------
extern "C" void kernel_launch(void* const* d_in, const int* in_sizes, int n_in,
                              void* d_out, int out_size)
{
    const float* l3 = (const float*)d_in[0];
    const float* l4 = (const float*)d_in[1];
    const float* l5 = (const float*)d_in[2];
    const float* gt = (const float*)d_in[3];

    const float *c3, *c4, *c5, *r3, *r4, *r5, *t3, *t4, *t5;
    if (in_sizes[5] == BATCH * N3 * 4) {
        c3 = (const float*)d_in[4];  r3 = (const float*)d_in[5];  t3 = (const float*)d_in[6];
        c4 = (const float*)d_in[7];  r4 = (const float*)d_in[8];  t4 = (const float*)d_in[9];
        c5 = (const float*)d_in[10]; r5 = (const float*)d_in[11]; t5 = (const float*)d_in[12];
    } else {
        c3 = (const float*)d_in[4];  c4 = (const float*)d_in[5];  c5 = (const float*)d_in[6];
        r3 = (const float*)d_in[7];  r4 = (const float*)d_in[8];  r5 = (const float*)d_in[9];
        t3 = (const float*)d_in[10]; t4 = (const float*)d_in[11]; t5 = (const float*)d_in[12];
    }

    float* out       = (float*)d_out;
    float* out_dets  = out;                                   // [16,1000,5]
    float* out_delta = out + (size_t)BATCH * TOPK * 5;        // [16,21504,4]
    float* out_ctr   = out_delta + (size_t)BATCH * NTOT * 4;  // [16,21504]

    const int nms_smem = 32 * SUPSTRIDE * sizeof(unsigned int);   // 132224 B
    cudaFuncSetAttribute(k_nms, cudaFuncAttributeMaxDynamicSharedMemorySize, nms_smem);

    dim3 grd(NTOT / 256, BATCH);
    k_fused<<<grd, 256>>>(l3, l4, l5, gt, c3, c4, c5, r3, r4, r5, t3, t4, t5,
                          out_delta, out_ctr);
    k_sel  <<<BATCH, 1024>>>();
    k_nms  <<<BATCH, 1024, nms_smem>>>(out_dets);
}

// round 6
// speedup vs baseline: 1.8702x; 1.1944x over previous
#include <cuda_runtime.h>
#include <math.h>

#define BATCH 16
#define NCLS  20
#define NGT   64
#define N3    16384
#define N4    4096
#define N5    1024
#define NTOT  (N3 + N4 + N5)     // 21504
#define SEG   (NTOT / 32)        // 672 elements per warp segment
#define TOPK  1000
#define MAXDET 100
#define SCORE_THR 0.3f
#define IOU_THR   0.5f
#define NBIN  4096
#define TB0   0x3E99999Au        // float bits of 0.3f
#define SUPSTRIDE 1033           // bank-conflict-free transposed stride

// ---------------- scratch (device globals; zero-initialized at load) --------
__device__ float        g_scores[BATCH * NTOT];
__device__ float4       g_boxes [BATCH * NTOT];
__device__ int          g_cls   [BATCH * NTOT];
__device__ unsigned int g_hist  [BATCH * NBIN];   // zeroed by k_post after use

__device__ __forceinline__ float sigmoidf_(float x) {
    if (x >= 0.f) return 1.f / (1.f + expf(-x));
    float e = expf(x);
    return e / (1.f + e);
}
__device__ __forceinline__ unsigned int fenc(float f) {
    unsigned int u = __float_as_uint(f);
    return (u & 0x80000000u) ? ~u : (u | 0x80000000u);
}
__device__ __forceinline__ float fdec(unsigned int e) {
    return (e & 0x80000000u) ? __uint_as_float(e & 0x7FFFFFFFu) : __uint_as_float(~e);
}

// =========== kernel 1: targets + score/decode + score histogram =============
__global__ __launch_bounds__(256) void k_fused(
    const float* __restrict__ l3, const float* __restrict__ l4, const float* __restrict__ l5,
    const float* __restrict__ gt,
    const float* __restrict__ c3, const float* __restrict__ c4, const float* __restrict__ c5,
    const float* __restrict__ r3, const float* __restrict__ r4, const float* __restrict__ r5,
    const float* __restrict__ t3, const float* __restrict__ t4, const float* __restrict__ t5,
    float4* __restrict__ od, float* __restrict__ oc)
{
    const int b   = blockIdx.y;
    const int tid = threadIdx.x;
    const int i   = blockIdx.x * 256 + tid;          // 84*256 == NTOT exactly

    __shared__ float4 sbox[NGT];
    __shared__ float  sarea[NGT];
    __shared__ int    swcnt[2];
    __shared__ int    scnt;

    // level params per block (blocks never straddle levels)
    float lower, upper, stride;
    if (blockIdx.x < 64)      { lower = 0.f;   upper = 64.f;     stride = 8.f;  }
    else if (blockIdx.x < 80) { lower = 64.f;  upper = 128.f;    stride = 16.f; }
    else                      { lower = 128.f; upper = INFINITY; stride = 32.f; }
    const float maxwh_hi = 2.0f * upper;   // INF for p5

    // ---- load + order-preserving compaction of valid & level-relevant boxes
    // necessary condition: maxd in (lower,upper) possible  <=>
    //   max(w,h) > lower  &&  max(w,h)/2 < upper   (maxd in [max(w,h)/2, max(w,h)))
    float x0 = 0.f, y0 = 0.f, x1 = 0.f, y1 = 0.f;
    bool  val = false;
    int   pref = 0;
    if (tid < 64) {
        const float* g = gt + (size_t)b * NGT * 5 + tid * 5;
        x0 = g[0]; y0 = g[1]; x1 = g[2]; y1 = g[3];
        float maxwh = fmaxf(x1 - x0, y1 - y0);
        val = (x0 >= 0.f) && (maxwh > lower) && (maxwh < maxwh_hi);
        int lane = tid & 31, w = tid >> 5;
        unsigned m = __ballot_sync(0xFFFFFFFFu, val);
        pref = __popc(m & ((1u << lane) - 1));
        if (lane == 0) swcnt[w] = __popc(m);
    }
    __syncthreads();
    if (tid < 64 && val) {
        int base = (tid >= 32) ? swcnt[0] : 0;
        int pos  = base + pref;
        sbox[pos]  = make_float4(x0, y0, x1, y1);
        sarea[pos] = (x1 - x0) * (y1 - y0);
    }
    if (tid == 0) scnt = swcnt[0] + swcnt[1];
    __syncthreads();

    int j, n;
    const float *locs, *cls, *reg, *ctr;
    if (i < N3)           { j = i;            n = N3; locs = l3; cls = c3; reg = r3; ctr = t3; }
    else if (i < N3 + N4) { j = i - N3;       n = N4; locs = l4; cls = c4; reg = r4; ctr = t4; }
    else                  { j = i - N3 - N4;  n = N5; locs = l5; cls = c5; reg = r5; ctr = t5; }
    float xc = locs[2*j], yc = locs[2*j+1];

    // ---- GT matching: min-area among eligible, first-wins on ties ----
    float bestA = INFINITY;
    int   besti = -1;
    const int nv = scnt;
    for (int m = 0; m < nv; m++) {
        float4 bb = sbox[m];
        float l = xc - bb.x, t = yc - bb.y, r = bb.z - xc, bo = bb.w - yc;
        float mn = fminf(fminf(l, t), fminf(r, bo));
        float mx = fmaxf(fmaxf(l, t), fmaxf(r, bo));
        float a  = sarea[m];
        if (mn > 0.f && mx > lower && mx < upper && a < bestA) { bestA = a; besti = m; }
    }

    float d0, d1, d2, d3, ctrt;
    if (besti < 0) {
        d0 = d1 = d2 = d3 = -1.f; ctrt = -1.f;
    } else {
        float4 bb = sbox[besti];
        d0 = (xc - bb.x) / stride;
        d1 = (yc - bb.y) / stride;
        d2 = (bb.z - xc) / stride;
        d3 = (bb.w - yc) / stride;
        float num = fminf(d0, d2) * fminf(d1, d3);
        float den = fmaxf(d0, d2) * fmaxf(d1, d3);
        ctrt = sqrtf(num / den);
    }
    size_t base = (size_t)(b * NTOT + i);
    od[base] = make_float4(d0, d1, d2, d3);
    oc[base] = ctrt;

    // ---- class-max score + decode ----
    const float4* cp4 = reinterpret_cast<const float4*>(cls + ((size_t)b * n + j) * NCLS);
    float best = -INFINITY; int bc = 0;
    #pragma unroll
    for (int c4i = 0; c4i < 5; c4i++) {
        float4 v = cp4[c4i];
        if (v.x > best) { best = v.x; bc = c4i*4+0; }
        if (v.y > best) { best = v.y; bc = c4i*4+1; }
        if (v.z > best) { best = v.z; bc = c4i*4+2; }
        if (v.w > best) { best = v.w; bc = c4i*4+3; }
    }
    float sc = sqrtf(sigmoidf_(best) * sigmoidf_(ctr[(size_t)b * n + j]));

    float4 rp = reinterpret_cast<const float4*>(reg)[(size_t)b * n + j];
    float e0 = fmaxf(rp.x, 0.f) * stride;
    float e1 = fmaxf(rp.y, 0.f) * stride;
    float e2 = fmaxf(rp.z, 0.f) * stride;
    float e3 = fmaxf(rp.w, 0.f) * stride;

    int o = b * NTOT + i;
    g_scores[o] = sc;
    g_boxes[o]  = make_float4(xc - e0, yc - e1, xc + e2, yc + e3);
    g_cls[o]    = bc;

    unsigned int sb = __float_as_uint(sc);
    if (sb > TB0) atomicAdd(&g_hist[b * NBIN + ((sb >> 13) & (NBIN-1))], 1u);
}

// ---- suppression sub-matrix rows/cols [0,L), transposed sup[w*1033+p] ------
// skipL: region (p < skipL && (w<<5) < skipL) already computed.
__device__ __forceinline__ void compute_sup(
    unsigned int* __restrict__ sup, const float4* __restrict__ nbox,
    const float* __restrict__ areas, int L, int lshift, int skipL, int tid)
{
    const int total = (L >> 5) * L;
    for (int u = tid; u < total; u += 1024) {
        int p = u & (L - 1);
        int w = u >> lshift;
        if (p < skipL && (w << 5) < skipL) continue;
        float4 pb = nbox[p];
        float  pa = areas[p];
        unsigned bits = 0;
        int jb = w << 5;
        #pragma unroll 8
        for (int jj = 0; jj < 32; ++jj) {
            float4 qb = nbox[jb + jj];
            float ar  = areas[jb + jj];
            float xx1 = fmaxf(pb.x, qb.x);
            float yy1 = fmaxf(pb.y, qb.y);
            float xx2 = fminf(pb.z, qb.z);
            float yy2 = fminf(pb.w, qb.w);
            float inter = fmaxf(xx2 - xx1, 0.f) * fmaxf(yy2 - yy1, 0.f);
            float uni   = pa + ar - inter;
            // iou>thr (uni>0) or 0/0=NaN (uni==0) -> suppressed. Division-free.
            if ((inter > IOU_THR * uni) || (uni == 0.f)) bits |= (1u << jj);
        }
        sup[w * SUPSTRIDE + p] = bits;
    }
}

// ---- warp-serial greedy walk over sorted order (ffs jumping) ----
__device__ __forceinline__ void walk(
    const unsigned int* __restrict__ sup, int nv, int L,
    unsigned int* __restrict__ skeep, int* __restrict__ esc, int lane)
{
    unsigned removed = 0, keepm = 0;
    int kept = 0; bool bad = false;
    for (int w = 0; w < 32 && kept < MAXDET; ++w) {
        int base = w << 5;
        if (base >= nv) break;
        if (base >= L) { bad = true; break; }
        int lim = min(32, nv - base);
        unsigned vmask = (lim == 32) ? 0xFFFFFFFFu : ((1u << lim) - 1u);
        unsigned cur  = __shfl_sync(0xFFFFFFFFu, removed, w);
        unsigned cand = ~cur & vmask;
        while (cand && kept < MAXDET) {
            int bit = __ffs(cand) - 1;
            int p = base + bit;
            if (lane == w) keepm |= (1u << bit);
            ++kept;
            removed |= sup[lane * SUPSTRIDE + p];
            cur  = __shfl_sync(0xFFFFFFFFu, removed, w);
            cand = ~cur & vmask & (0xFFFFFFFEu << bit);
        }
    }
    skeep[lane] = keepm;
    if (lane == 0 && bad) *esc = 1;
}

// =========== kernel 2: rank-scatter top-k + in-smem NMS + det write =========
// dynamic smem layout (total 169088 B):
//   [0,132224)        sup (32 x 1033 words)  — aliases shist[4096]+suf[4096]
//   [132224,148608)   keys[2048] u64
//   [148608,164992)   nbox[1024] float4
//   [164992,169088)   areas[1024] float
__global__ __launch_bounds__(1024) void k_post(float* __restrict__ dets)
{
    extern __shared__ unsigned char dyn[];
    unsigned int*       shist = (unsigned int*)dyn;              // [4096]
    unsigned int*       suf   = (unsigned int*)(dyn + 16384);    // [4096]
    unsigned int*       sup   = (unsigned int*)dyn;              // NMS phase
    unsigned long long* keys  = (unsigned long long*)(dyn + 132224);
    float4*             nbox  = (float4*)(dyn + 148608);
    float*              areas = (float*)(dyn + 164992);

    __shared__ unsigned int wsum[32], wAbove[32], skeep[32];
    __shared__ unsigned int sMaxU, sMaxBin;
    __shared__ int sB, sB2, sTotal, sCand, sAbove, sEsc1, sEsc2, sEsc3;

    const int b    = blockIdx.x;
    const int tid  = threadIdx.x;
    const int lane = tid & 31, wid = tid >> 5;
    const float* sc = g_scores + b * NTOT;

    // ---- phase 1: pull histogram, zero global copy for next replay ----
    for (int k = tid; k < NBIN; k += 1024) {
        unsigned v = g_hist[b * NBIN + k];
        shist[k] = v;
        g_hist[b * NBIN + k] = 0;
    }
    if (tid == 0) {
        sB = 0; sB2 = 0; sCand = 0; sAbove = 0; sMaxBin = 0;
        sEsc1 = 0; sEsc2 = 0; sEsc3 = 0; sMaxU = fenc(0.0f);
    }
    __syncthreads();

    // ---- phase 2: suffix scan -> threshold bin B + per-bin start slots ----
    unsigned s0 = shist[4*tid], s1 = shist[4*tid+1], s2 = shist[4*tid+2], s3 = shist[4*tid+3];
    unsigned st = s0 + s1 + s2 + s3;
    unsigned inc = st;
    #pragma unroll
    for (int off = 1; off < 32; off <<= 1) {
        unsigned v = __shfl_down_sync(0xFFFFFFFFu, inc, off);
        if (lane + off < 32) inc += v;
    }
    if (lane == 0) wsum[wid] = inc;
    __syncthreads();
    if (tid < 32) {
        unsigned v = wsum[tid], winc = v;
        #pragma unroll
        for (int off = 1; off < 32; off <<= 1) {
            unsigned u = __shfl_down_sync(0xFFFFFFFFu, winc, off);
            if (tid + off < 32) winc += u;
        }
        wAbove[tid] = winc - v;
        if (tid == 0) sTotal = (int)winc;
    }
    __syncthreads();
    {
        unsigned cum = wAbove[wid] + (inc - st);      // strictly above my 4-bin chunk
        unsigned hh[4] = { s3, s2, s1, s0 };
        #pragma unroll
        for (int q = 0; q < 4; q++) {
            int bin = 4*tid + 3 - q;
            suf[bin] = cum;                           // # keys in bins > bin
            if (cum < TOPK && cum + hh[q] >= TOPK) {
                sB = bin; sCand = (int)(cum + hh[q]); sAbove = (int)cum;
            }
            cum += hh[q];
        }
    }
    __syncthreads();
    if (sTotal < TOPK) {                // uniform: take everything > 0.3
        if (tid == 0) sCand = sTotal;
        __syncthreads();
    }
    const int B = sB;
    int B2 = 0;

    // ---- rare refinement: boundary bin too fat for the 2048-key buffer ----
    if (sCand > 2040) {
        unsigned* h2 = (unsigned*)keys;
        for (int k = tid; k < 2048; k += 1024) h2[k] = 0;
        __syncthreads();
        for (int k = tid; k < NTOT; k += 1024) {
            unsigned bits = __float_as_uint(sc[k]);
            if (bits > TB0 && (int)((bits >> 13) & (NBIN-1)) == B)
                atomicAdd(&h2[(bits >> 2) & 2047u], 1u);
        }
        __syncthreads();
        if (tid == 0) {
            unsigned cum2 = (unsigned)sAbove; int bb = 0;
            for (int k = 2047; k >= 0; k--) {
                if (cum2 + h2[k] >= TOPK) { bb = k; break; }
                cum2 += h2[k];
            }
            sB2 = bb;
        }
        __syncthreads();
        B2 = sB2;
        __syncthreads();
    }

    // ---- phase 2b: max bin occupancy among candidate bins ----
    {
        unsigned mb = 0;
        #pragma unroll
        for (int q = 0; q < 4; q++) {
            int bin = 4*tid + q;
            if (bin >= B) mb = max(mb, shist[bin]);
        }
        #pragma unroll
        for (int off = 16; off > 0; off >>= 1)
            mb = max(mb, __shfl_down_sync(0xFFFFFFFFu, mb, off));
        if (lane == 0) atomicMax(&sMaxBin, mb);
    }

    // ---- phase 3: zero keys, then direct rank-scatter ----
    for (int k = tid; k < 2048; k += 1024) keys[k] = 0ull;
    __syncthreads();
    const unsigned maxbin = (B2 > 0) ? 9999u : sMaxBin;   // refined case -> bitonic
    for (int it = 0; it < SEG / 32; it++) {
        int k = wid * SEG + it * 32 + lane;
        unsigned bits = __float_as_uint(sc[k]);
        int bin = (int)((bits >> 13) & (NBIN-1));
        bool cand = (bits > TB0) && (bin > B || (bin == B && (int)((bits >> 2) & 2047u) >= B2));
        if (cand) {
            unsigned pos = atomicAdd(&suf[bin], 1u);   // slot within bin region (desc)
            if (pos < 2048)
                keys[pos] = ((unsigned long long)bits << 32)
                          | (unsigned long long)(0xFFFFFFFFu - (unsigned)k);
        }
    }
    __syncthreads();

    // ---- phase 4: finalize order (descending, rank r at keys[r]) ----
    if (maxbin <= 12u) {
        // within-bin fix-up: odd-even transposition, bounded by bin size
        int passes = 2 * (int)maxbin + 2;
        for (int ps = 0; ps < passes; ps++) {
            int i2 = 2 * tid + (ps & 1);
            if (i2 + 1 < 2048) {
                unsigned long long a = keys[i2], c = keys[i2+1];
                if (a < c) { keys[i2] = c; keys[i2+1] = a; }
            }
            __syncthreads();
        }
    } else {
        // full bitonic sort DESCENDING over 2048
        for (unsigned ksz = 2; ksz <= 2048; ksz <<= 1) {
            for (unsigned jj = ksz >> 1; jj > 0; jj >>= 1) {
                for (unsigned idx = tid; idx < 2048; idx += 1024) {
                    unsigned ixj = idx ^ jj;
                    if (ixj > idx) {
                        unsigned long long a = keys[idx], c = keys[ixj];
                        bool up = ((idx & ksz) == 0);
                        if (up ? (a < c) : (a > c)) { keys[idx] = c; keys[ixj] = a; }
                    }
                }
                if (jj >= 16) __syncthreads();
                else __syncwarp();
            }
            __syncthreads();
        }
    }

    // ---- phase 5: gather top-1000, max_coord ----
    unsigned long long key = (tid < TOPK) ? keys[tid] : 0ull;
    float s = __uint_as_float((unsigned)(key >> 32));
    unsigned gidx = 0xFFFFFFFFu - (unsigned)key;
    bool valid = (tid < TOPK) && (key != 0ull);
    float4 bx = make_float4(0.f, 0.f, 0.f, 0.f);
    int cid = 0;
    if (valid) { bx = g_boxes[b * NTOT + gidx]; cid = g_cls[b * NTOT + gidx]; }
    float mrow = valid ? fmaxf(fmaxf(bx.x, bx.y), fmaxf(bx.z, bx.w)) : 0.f;
    {
        unsigned e = fenc(mrow);
        #pragma unroll
        for (int off = 16; off > 0; off >>= 1)
            e = max(e, __shfl_down_sync(0xFFFFFFFFu, e, off));
        if (lane == 0) atomicMax(&sMaxU, e);
    }
    int NVraw = __syncthreads_count(valid);
    const int NV = min(NVraw, TOPK);
    const float offmul = fdec(sMaxU) + 1.0f;
    if (tid < TOPK) {
        float o = (float)cid * offmul;
        float4 nb = make_float4(bx.x + o, bx.y + o, bx.z + o, bx.w + o);
        nbox[tid]  = nb;
        areas[tid] = (nb.z - nb.x) * (nb.w - nb.y);
    } else if (tid < 1024) {
        nbox[tid]  = make_float4(0.f, 0.f, 0.f, 0.f);
        areas[tid] = 0.f;
    }
    __syncthreads();    // nbox/areas ready; sup may now overwrite shist/suf

    // ---- phase 6: NMS ladder 256 -> 512 -> 1024 ----
    compute_sup(sup, nbox, areas, 256, 8, 0, tid);
    __syncthreads();
    if (tid < 32) walk(sup, NV, 256, skeep, &sEsc1, tid);
    __syncthreads();
    if (sEsc1) {
        compute_sup(sup, nbox, areas, 512, 9, 256, tid);
        __syncthreads();
        if (tid < 32) walk(sup, NV, 512, skeep, &sEsc2, tid);
        __syncthreads();
        if (sEsc2) {
            compute_sup(sup, nbox, areas, 1024, 10, 512, tid);
            __syncthreads();
            if (tid < 32) walk(sup, NV, 1024, skeep, &sEsc3, tid);
            __syncthreads();
        }
    }

    // ---- phase 7: write detections ----
    if (tid < TOPK) {
        float* det = dets + (size_t)b * TOPK * 5 + (size_t)tid * 5;
        if ((skeep[tid >> 5] >> (tid & 31)) & 1u) {
            det[0] = bx.x; det[1] = bx.y; det[2] = bx.z; det[3] = bx.w; det[4] = s;
        } else {
            det[0] = 0.f; det[1] = 0.f; det[2] = 0.f; det[3] = 0.f; det[4] = 0.f;
        }
    }
}

// ---------------- launch ----------------------------------------------------
extern "C" void kernel_launch(void* const* d_in, const int* in_sizes, int n_in,
                              void* d_out, int out_size)
{
    const float* l3 = (const float*)d_in[0];
    const float* l4 = (const float*)d_in[1];
    const float* l5 = (const float*)d_in[2];
    const float* gt = (const float*)d_in[3];

    const float *c3, *c4, *c5, *r3, *r4, *r5, *t3, *t4, *t5;
    if (in_sizes[5] == BATCH * N3 * 4) {
        c3 = (const float*)d_in[4];  r3 = (const float*)d_in[5];  t3 = (const float*)d_in[6];
        c4 = (const float*)d_in[7];  r4 = (const float*)d_in[8];  t4 = (const float*)d_in[9];
        c5 = (const float*)d_in[10]; r5 = (const float*)d_in[11]; t5 = (const float*)d_in[12];
    } else {
        c3 = (const float*)d_in[4];  c4 = (const float*)d_in[5];  c5 = (const float*)d_in[6];
        r3 = (const float*)d_in[7];  r4 = (const float*)d_in[8];  r5 = (const float*)d_in[9];
        t3 = (const float*)d_in[10]; t4 = (const float*)d_in[11]; t5 = (const float*)d_in[12];
    }

    float* out       = (float*)d_out;
    float* out_dets  = out;                                   // [16,1000,5]
    float* out_delta = out + (size_t)BATCH * TOPK * 5;        // [16,21504,4] (16B aligned)
    float* out_ctr   = out_delta + (size_t)BATCH * NTOT * 4;  // [16,21504]

    const int post_smem = 169088;
    cudaFuncSetAttribute(k_post, cudaFuncAttributeMaxDynamicSharedMemorySize, post_smem);

    dim3 grd(NTOT / 256, BATCH);
    k_fused<<<grd, 256>>>(l3, l4, l5, gt, c3, c4, c5, r3, r4, r5, t3, t4, t5,
                          (float4*)out_delta, out_ctr);
    k_post <<<BATCH, 1024, post_smem>>>(out_dets);
}

// round 7
// speedup vs baseline: 2.1743x; 1.1626x over previous
#include <cuda_runtime.h>
#include <math.h>

#define BATCH 16
#define NCLS  20
#define NGT   64
#define N3    16384
#define N4    4096
#define N5    1024
#define NTOT  (N3 + N4 + N5)     // 21504
#define SEG   (NTOT / 32)        // 672 elements per warp segment
#define TOPK  1000
#define MAXDET 100
#define SCORE_THR 0.3f
#define IOU_THR   0.5f
#define NBIN  4096
#define TB0   0x3E99999Au        // float bits of 0.3f
#define SUPSTRIDE 1033           // bank-conflict-free transposed stride

// ---------------- scratch (device globals; zero-initialized at load) --------
__device__ float        g_scores[BATCH * NTOT];
__device__ float4       g_boxes [BATCH * NTOT];
__device__ int          g_cls   [BATCH * NTOT];
__device__ unsigned int g_hist  [BATCH * NBIN];   // zeroed by k_post after use

__device__ __forceinline__ float sigmoidf_(float x) {
    if (x >= 0.f) return 1.f / (1.f + expf(-x));
    float e = expf(x);
    return e / (1.f + e);
}
__device__ __forceinline__ unsigned int fenc(float f) {
    unsigned int u = __float_as_uint(f);
    return (u & 0x80000000u) ? ~u : (u | 0x80000000u);
}
__device__ __forceinline__ float fdec(unsigned int e) {
    return (e & 0x80000000u) ? __uint_as_float(e & 0x7FFFFFFFu) : __uint_as_float(~e);
}

// =========== kernel 1: targets + score/decode + score histogram =============
__global__ __launch_bounds__(256) void k_fused(
    const float* __restrict__ l3, const float* __restrict__ l4, const float* __restrict__ l5,
    const float* __restrict__ gt,
    const float* __restrict__ c3, const float* __restrict__ c4, const float* __restrict__ c5,
    const float* __restrict__ r3, const float* __restrict__ r4, const float* __restrict__ r5,
    const float* __restrict__ t3, const float* __restrict__ t4, const float* __restrict__ t5,
    float4* __restrict__ od, float* __restrict__ oc)
{
    const int b   = blockIdx.y;
    const int tid = threadIdx.x;
    const int i   = blockIdx.x * 256 + tid;          // 84*256 == NTOT exactly

    __shared__ float4 sbox[NGT];
    __shared__ float  sarea[NGT];
    __shared__ int    swcnt[2];
    __shared__ int    scnt;

    float lower, upper, stride;
    if (blockIdx.x < 64)      { lower = 0.f;   upper = 64.f;     stride = 8.f;  }
    else if (blockIdx.x < 80) { lower = 64.f;  upper = 128.f;    stride = 16.f; }
    else                      { lower = 128.f; upper = INFINITY; stride = 32.f; }
    const float maxwh_hi = 2.0f * upper;

    // prefilter: maxd in (lower,upper) possible  <=>  max(w,h) > lower && max(w,h)/2 < upper
    float x0 = 0.f, y0 = 0.f, x1 = 0.f, y1 = 0.f;
    bool  val = false;
    int   pref = 0;
    if (tid < 64) {
        const float* g = gt + (size_t)b * NGT * 5 + tid * 5;
        x0 = g[0]; y0 = g[1]; x1 = g[2]; y1 = g[3];
        float maxwh = fmaxf(x1 - x0, y1 - y0);
        val = (x0 >= 0.f) && (maxwh > lower) && (maxwh < maxwh_hi);
        int lane = tid & 31, w = tid >> 5;
        unsigned m = __ballot_sync(0xFFFFFFFFu, val);
        pref = __popc(m & ((1u << lane) - 1));
        if (lane == 0) swcnt[w] = __popc(m);
    }
    __syncthreads();
    if (tid < 64 && val) {
        int base = (tid >= 32) ? swcnt[0] : 0;
        int pos  = base + pref;
        sbox[pos]  = make_float4(x0, y0, x1, y1);
        sarea[pos] = (x1 - x0) * (y1 - y0);
    }
    if (tid == 0) scnt = swcnt[0] + swcnt[1];
    __syncthreads();

    int j, n;
    const float *locs, *cls, *reg, *ctr;
    if (i < N3)           { j = i;            n = N3; locs = l3; cls = c3; reg = r3; ctr = t3; }
    else if (i < N3 + N4) { j = i - N3;       n = N4; locs = l4; cls = c4; reg = r4; ctr = t4; }
    else                  { j = i - N3 - N4;  n = N5; locs = l5; cls = c5; reg = r5; ctr = t5; }
    float xc = locs[2*j], yc = locs[2*j+1];

    float bestA = INFINITY;
    int   besti = -1;
    const int nv = scnt;
    for (int m = 0; m < nv; m++) {
        float4 bb = sbox[m];
        float l = xc - bb.x, t = yc - bb.y, r = bb.z - xc, bo = bb.w - yc;
        float mn = fminf(fminf(l, t), fminf(r, bo));
        float mx = fmaxf(fmaxf(l, t), fmaxf(r, bo));
        float a  = sarea[m];
        if (mn > 0.f && mx > lower && mx < upper && a < bestA) { bestA = a; besti = m; }
    }

    float d0, d1, d2, d3, ctrt;
    if (besti < 0) {
        d0 = d1 = d2 = d3 = -1.f; ctrt = -1.f;
    } else {
        float4 bb = sbox[besti];
        d0 = (xc - bb.x) / stride;
        d1 = (yc - bb.y) / stride;
        d2 = (bb.z - xc) / stride;
        d3 = (bb.w - yc) / stride;
        float num = fminf(d0, d2) * fminf(d1, d3);
        float den = fmaxf(d0, d2) * fmaxf(d1, d3);
        ctrt = sqrtf(num / den);
    }
    size_t base = (size_t)(b * NTOT + i);
    od[base] = make_float4(d0, d1, d2, d3);
    oc[base] = ctrt;

    const float4* cp4 = reinterpret_cast<const float4*>(cls + ((size_t)b * n + j) * NCLS);
    float best = -INFINITY; int bc = 0;
    #pragma unroll
    for (int c4i = 0; c4i < 5; c4i++) {
        float4 v = cp4[c4i];
        if (v.x > best) { best = v.x; bc = c4i*4+0; }
        if (v.y > best) { best = v.y; bc = c4i*4+1; }
        if (v.z > best) { best = v.z; bc = c4i*4+2; }
        if (v.w > best) { best = v.w; bc = c4i*4+3; }
    }
    float sc = sqrtf(sigmoidf_(best) * sigmoidf_(ctr[(size_t)b * n + j]));

    float4 rp = reinterpret_cast<const float4*>(reg)[(size_t)b * n + j];
    float e0 = fmaxf(rp.x, 0.f) * stride;
    float e1 = fmaxf(rp.y, 0.f) * stride;
    float e2 = fmaxf(rp.z, 0.f) * stride;
    float e3 = fmaxf(rp.w, 0.f) * stride;

    int o = b * NTOT + i;
    g_scores[o] = sc;
    g_boxes[o]  = make_float4(xc - e0, yc - e1, xc + e2, yc + e3);
    g_cls[o]    = bc;

    unsigned int sb = __float_as_uint(sc);
    if (sb > TB0) atomicAdd(&g_hist[b * NBIN + ((sb >> 13) & (NBIN-1))], 1u);
}

// ---- symmetric suppression band: tiles tr<=tc with tc in [Ts,Tn) ----------
// computes tile (tr,tc) directly and mirrors to (tc,tr) via bit transpose.
__device__ __forceinline__ void sup_band(
    unsigned int* __restrict__ sup, const float4* __restrict__ nbox,
    const float* __restrict__ areas, int Ts, int Tn, int wid, int lane)
{
    const int g0 = (Ts * (Ts + 1)) >> 1;
    const int g1 = (Tn * (Tn + 1)) >> 1;
    for (int g = g0 + wid; g < g1; g += 32) {
        int tc = (int)((sqrtf(8.0f * (float)g + 1.0f) - 1.0f) * 0.5f);
        if (((tc * (tc + 1)) >> 1) > g) tc--;
        else if ((((tc + 1) * (tc + 2)) >> 1) <= g) tc++;
        int tr = g - ((tc * (tc + 1)) >> 1);

        int p = (tr << 5) + lane;              // row (per lane)
        float4 pb = nbox[p];
        float  pa = areas[p];
        unsigned bits = 0;
        int jb = tc << 5;
        #pragma unroll 8
        for (int jj = 0; jj < 32; ++jj) {
            float4 qb = nbox[jb + jj];         // uniform -> broadcast
            float ar  = areas[jb + jj];
            float xx1 = fmaxf(pb.x, qb.x);
            float yy1 = fmaxf(pb.y, qb.y);
            float xx2 = fminf(pb.z, qb.z);
            float yy2 = fminf(pb.w, qb.w);
            float inter = fmaxf(xx2 - xx1, 0.f) * fmaxf(yy2 - yy1, 0.f);
            float uni   = pa + ar - inter;
            if ((inter > IOU_THR * uni) || (uni == 0.f)) bits |= (1u << jj);
        }
        sup[tc * SUPSTRIDE + p] = bits;
        if (tr != tc) {                        // mirror via 32x32 bit transpose
            unsigned tw = 0;
            #pragma unroll
            for (int k2 = 0; k2 < 32; ++k2) {
                unsigned bb = __ballot_sync(0xFFFFFFFFu, (bits >> k2) & 1u);
                if (lane == k2) tw = bb;
            }
            sup[tr * SUPSTRIDE + ((tc << 5) + lane)] = tw;
        }
    }
}

// ---- warp-serial greedy walk over sorted order (ffs jumping) ----
__device__ __forceinline__ void walk(
    const unsigned int* __restrict__ sup, int nv, int L,
    unsigned int* __restrict__ skeep, int* __restrict__ esc, int lane)
{
    unsigned removed = 0, keepm = 0;
    int kept = 0; bool bad = false;
    for (int w = 0; w < 32 && kept < MAXDET; ++w) {
        int base = w << 5;
        if (base >= nv) break;
        if (base >= L) { bad = true; break; }
        int lim = min(32, nv - base);
        unsigned vmask = (lim == 32) ? 0xFFFFFFFFu : ((1u << lim) - 1u);
        unsigned cur  = __shfl_sync(0xFFFFFFFFu, removed, w);
        unsigned cand = ~cur & vmask;
        while (cand && kept < MAXDET) {
            int bit = __ffs(cand) - 1;
            int p = base + bit;
            if (lane == w) keepm |= (1u << bit);
            ++kept;
            removed |= sup[lane * SUPSTRIDE + p];
            cur  = __shfl_sync(0xFFFFFFFFu, removed, w);
            cand = ~cur & vmask & (0xFFFFFFFEu << bit);
        }
    }
    skeep[lane] = keepm;
    if (lane == 0 && bad) *esc = 1;
}

// =========== kernel 2: rank-scatter top-k + per-bin sort + NMS ==============
// dynamic smem (total 169088 B):
//   [0,132224)      sup (32 x 1033 words); aliases shist[4096]/suf[4096]/suf0[4096]
//   [132224,148608) keys[2048] u64
//   [148608,164992) nbox[1024] float4
//   [164992,169088) areas[1024] float
__global__ __launch_bounds__(1024) void k_post(float* __restrict__ dets)
{
    extern __shared__ unsigned char dyn[];
    unsigned int*       shist = (unsigned int*)dyn;              // [4096]
    unsigned int*       suf   = (unsigned int*)(dyn + 16384);    // [4096]
    unsigned int*       suf0  = (unsigned int*)(dyn + 32768);    // [4096]
    unsigned int*       sup   = (unsigned int*)dyn;              // NMS phase
    unsigned long long* keys  = (unsigned long long*)(dyn + 132224);
    float4*             nbox  = (float4*)(dyn + 148608);
    float*              areas = (float*)(dyn + 164992);

    __shared__ unsigned int wsum[32], wAbove[32], skeep[32];
    __shared__ unsigned int sMaxU;
    __shared__ int sB, sB2, sTotal, sCand, sAbove, sBig;
    __shared__ int sEsc1, sEsc2, sEsc3, sEsc4;

    const int b    = blockIdx.x;
    const int tid  = threadIdx.x;
    const int lane = tid & 31, wid = tid >> 5;
    const float* sc = g_scores + b * NTOT;

    // ---- phase 1: pull histogram, zero global copy for next replay ----
    for (int k = tid; k < NBIN; k += 1024) {
        unsigned v = g_hist[b * NBIN + k];
        shist[k] = v;
        g_hist[b * NBIN + k] = 0;
    }
    if (tid == 0) {
        sB = 0; sB2 = 0; sCand = 0; sAbove = 0; sBig = 0;
        sEsc1 = 0; sEsc2 = 0; sEsc3 = 0; sEsc4 = 0; sMaxU = fenc(0.0f);
    }
    __syncthreads();

    // ---- phase 2: suffix scan -> threshold bin B + per-bin start slots ----
    unsigned s0 = shist[4*tid], s1 = shist[4*tid+1], s2 = shist[4*tid+2], s3 = shist[4*tid+3];
    unsigned st = s0 + s1 + s2 + s3;
    unsigned inc = st;
    #pragma unroll
    for (int off = 1; off < 32; off <<= 1) {
        unsigned v = __shfl_down_sync(0xFFFFFFFFu, inc, off);
        if (lane + off < 32) inc += v;
    }
    if (lane == 0) wsum[wid] = inc;
    __syncthreads();
    if (tid < 32) {
        unsigned v = wsum[tid], winc = v;
        #pragma unroll
        for (int off = 1; off < 32; off <<= 1) {
            unsigned u = __shfl_down_sync(0xFFFFFFFFu, winc, off);
            if (tid + off < 32) winc += u;
        }
        wAbove[tid] = winc - v;
        if (tid == 0) sTotal = (int)winc;
    }
    __syncthreads();
    {
        unsigned cum = wAbove[wid] + (inc - st);
        unsigned hh[4] = { s3, s2, s1, s0 };
        #pragma unroll
        for (int q = 0; q < 4; q++) {
            int bin = 4*tid + 3 - q;
            suf[bin]  = cum;                  // scatter base (keys in bins > bin)
            suf0[bin] = cum;                  // saved start for per-bin sort
            if (cum < TOPK && cum + hh[q] >= TOPK) {
                sB = bin; sCand = (int)(cum + hh[q]); sAbove = (int)cum;
            }
            cum += hh[q];
        }
    }
    __syncthreads();
    if (sTotal < TOPK) {
        if (tid == 0) sCand = sTotal;
        __syncthreads();
    }
    const int B = sB;
    int B2 = 0;

    // ---- rare refinement: boundary bin too fat for the 2048-key buffer ----
    if (sCand > 2040) {
        unsigned* h2 = (unsigned*)keys;
        for (int k = tid; k < 2048; k += 1024) h2[k] = 0;
        __syncthreads();
        for (int k = tid; k < NTOT; k += 1024) {
            unsigned bits = __float_as_uint(sc[k]);
            if (bits > TB0 && (int)((bits >> 13) & (NBIN-1)) == B)
                atomicAdd(&h2[(bits >> 2) & 2047u], 1u);
        }
        __syncthreads();
        if (tid == 0) {
            unsigned cum2 = (unsigned)sAbove; int bb = 0;
            for (int k = 2047; k >= 0; k--) {
                if (cum2 + h2[k] >= TOPK) { bb = k; break; }
                cum2 += h2[k];
            }
            sB2 = bb;
        }
        __syncthreads();
        B2 = sB2;
        __syncthreads();
    }

    // ---- phase 3: zero keys, then rank-scatter into bin regions ----
    for (int k = tid; k < 2048; k += 1024) keys[k] = 0ull;
    __syncthreads();
    for (int it = 0; it < SEG / 32; it++) {
        int k = wid * SEG + it * 32 + lane;
        unsigned bits = __float_as_uint(sc[k]);
        int bin = (int)((bits >> 13) & (NBIN-1));
        bool cand = (bits > TB0) && (bin > B || (bin == B && (int)((bits >> 2) & 2047u) >= B2));
        if (cand) {
            unsigned pos = atomicAdd(&suf[bin], 1u);
            if (pos < 2048)
                keys[pos] = ((unsigned long long)bits << 32)
                          | (unsigned long long)(0xFFFFFFFFu - (unsigned)k);
        }
    }
    __syncthreads();

    // ---- phase 4: per-bin warp-local sort (descending), no block barriers --
    {
        bool big = false;
        for (int bin = B + wid; bin < NBIN; bin += 32) {
            unsigned start = min(suf0[bin], 2048u);
            unsigned end   = min(suf[bin],  2048u);
            int cnt = (int)(end - start);
            if (cnt >= 2) {
                if (cnt <= 32) {
                    unsigned long long k64 = (lane < cnt) ? keys[start + lane] : 0ull;
                    #pragma unroll
                    for (int sz = 2; sz <= 32; sz <<= 1) {
                        for (int off = sz >> 1; off > 0; off >>= 1) {
                            unsigned long long o = __shfl_xor_sync(0xFFFFFFFFu, k64, off);
                            bool lower = (lane & off) == 0;
                            bool ascb  = (lane & sz) != 0;
                            bool keepmax = lower ^ ascb;
                            bool gt = k64 > o;
                            k64 = (keepmax == gt) ? k64 : o;
                        }
                    }
                    if (lane < cnt) keys[start + lane] = k64;
                } else big = true;
            }
        }
        if (__ballot_sync(0xFFFFFFFFu, big) && lane == 0) sBig = 1;
    }
    __syncthreads();
    if (sBig) {   // fallback: full descending bitonic over 2048
        for (unsigned ksz = 2; ksz <= 2048; ksz <<= 1) {
            for (unsigned jj = ksz >> 1; jj > 0; jj >>= 1) {
                for (unsigned idx = tid; idx < 2048; idx += 1024) {
                    unsigned ixj = idx ^ jj;
                    if (ixj > idx) {
                        unsigned long long a = keys[idx], c = keys[ixj];
                        bool up = ((idx & ksz) == 0);
                        if (up ? (a < c) : (a > c)) { keys[idx] = c; keys[ixj] = a; }
                    }
                }
                if (jj >= 16) __syncthreads();
                else __syncwarp();
            }
            __syncthreads();
        }
    }

    // ---- phase 5: gather top-1000, max_coord, offset boxes ----
    unsigned long long key = (tid < TOPK) ? keys[tid] : 0ull;
    float s = __uint_as_float((unsigned)(key >> 32));
    unsigned gidx = 0xFFFFFFFFu - (unsigned)key;
    bool valid = (tid < TOPK) && (key != 0ull);
    float4 bx = make_float4(0.f, 0.f, 0.f, 0.f);
    int cid = 0;
    if (valid) { bx = g_boxes[b * NTOT + gidx]; cid = g_cls[b * NTOT + gidx]; }
    float mrow = valid ? fmaxf(fmaxf(bx.x, bx.y), fmaxf(bx.z, bx.w)) : 0.f;
    {
        unsigned e = fenc(mrow);
        #pragma unroll
        for (int off = 16; off > 0; off >>= 1)
            e = max(e, __shfl_down_sync(0xFFFFFFFFu, e, off));
        if (lane == 0) atomicMax(&sMaxU, e);
    }
    int NVraw = __syncthreads_count(valid);
    const int NV = min(NVraw, TOPK);
    const float offmul = fdec(sMaxU) + 1.0f;
    if (tid < TOPK) {
        float o = (float)cid * offmul;
        float4 nb = make_float4(bx.x + o, bx.y + o, bx.z + o, bx.w + o);
        nbox[tid]  = nb;
        areas[tid] = (nb.z - nb.x) * (nb.w - nb.y);
    } else if (tid < 1024) {
        nbox[tid]  = make_float4(0.f, 0.f, 0.f, 0.f);
        areas[tid] = 0.f;
    }
    __syncthreads();    // nbox/areas ready; sup may now overwrite shist/suf/suf0

    // ---- phase 6: symmetric NMS ladder 256 -> 512 -> 768 -> 1024 ----
    sup_band(sup, nbox, areas, 0, 8, wid, lane);
    __syncthreads();
    if (tid < 32) walk(sup, NV, 256, skeep, &sEsc1, tid);
    __syncthreads();
    if (sEsc1) {
        sup_band(sup, nbox, areas, 8, 16, wid, lane);
        __syncthreads();
        if (tid < 32) walk(sup, NV, 512, skeep, &sEsc2, tid);
        __syncthreads();
        if (sEsc2) {
            sup_band(sup, nbox, areas, 16, 24, wid, lane);
            __syncthreads();
            if (tid < 32) walk(sup, NV, 768, skeep, &sEsc3, tid);
            __syncthreads();
            if (sEsc3) {
                sup_band(sup, nbox, areas, 24, 32, wid, lane);
                __syncthreads();
                if (tid < 32) walk(sup, NV, 1024, skeep, &sEsc4, tid);
                __syncthreads();
            }
        }
    }

    // ---- phase 7: write detections ----
    if (tid < TOPK) {
        float* det = dets + (size_t)b * TOPK * 5 + (size_t)tid * 5;
        if ((skeep[tid >> 5] >> (tid & 31)) & 1u) {
            det[0] = bx.x; det[1] = bx.y; det[2] = bx.z; det[3] = bx.w; det[4] = s;
        } else {
            det[0] = 0.f; det[1] = 0.f; det[2] = 0.f; det[3] = 0.f; det[4] = 0.f;
        }
    }
}

// ---------------- launch ----------------------------------------------------
extern "C" void kernel_launch(void* const* d_in, const int* in_sizes, int n_in,
                              void* d_out, int out_size)
{
    const float* l3 = (const float*)d_in[0];
    const float* l4 = (const float*)d_in[1];
    const float* l5 = (const float*)d_in[2];
    const float* gt = (const float*)d_in[3];

    const float *c3, *c4, *c5, *r3, *r4, *r5, *t3, *t4, *t5;
    if (in_sizes[5] == BATCH * N3 * 4) {
        c3 = (const float*)d_in[4];  r3 = (const float*)d_in[5];  t3 = (const float*)d_in[6];
        c4 = (const float*)d_in[7];  r4 = (const float*)d_in[8];  t4 = (const float*)d_in[9];
        c5 = (const float*)d_in[10]; r5 = (const float*)d_in[11]; t5 = (const float*)d_in[12];
    } else {
        c3 = (const float*)d_in[4];  c4 = (const float*)d_in[5];  c5 = (const float*)d_in[6];
        r3 = (const float*)d_in[7];  r4 = (const float*)d_in[8];  r5 = (const float*)d_in[9];
        t3 = (const float*)d_in[10]; t4 = (const float*)d_in[11]; t5 = (const float*)d_in[12];
    }

    float* out       = (float*)d_out;
    float* out_dets  = out;                                   // [16,1000,5]
    float* out_delta = out + (size_t)BATCH * TOPK * 5;        // [16,21504,4]
    float* out_ctr   = out_delta + (size_t)BATCH * NTOT * 4;  // [16,21504]

    const int post_smem = 169088;
    cudaFuncSetAttribute(k_post, cudaFuncAttributeMaxDynamicSharedMemorySize, post_smem);

    dim3 grd(NTOT / 256, BATCH);
    k_fused<<<grd, 256>>>(l3, l4, l5, gt, c3, c4, c5, r3, r4, r5, t3, t4, t5,
                          (float4*)out_delta, out_ctr);
    k_post <<<BATCH, 1024, post_smem>>>(out_dets);
}